// round 1
// baseline (speedup 1.0000x reference)
#include <cuda_runtime.h>

#define Nn 50000
#define Ee 800000
#define INF 256
#define OUTF 128
#define NEG_SLOPE 0.2f
#define ALPHA 0.5f

// Scratch (static device globals; no runtime allocation)
__device__ float    g_ft[(size_t)Nn * OUTF];   // fc projection [N,128]
__device__ float    g_el[Nn];
__device__ float    g_er[Nn];
__device__ unsigned g_me[Nn];                  // encoded segment max of e
__device__ unsigned g_mw[Nn];                  // encoded segment max of w
__device__ float    g_se[Nn];                  // segment sum exp(e - max)
__device__ float    g_sw[Nn];                  // segment sum exp(w - max)
__device__ float    g_e[Ee];                   // leaky-relu edge scores
__device__ float    g_z[Ee];                   // exp(e - max)
__device__ float    g_zw[Ee];                  // exp(w - max)

// Order-preserving float <-> uint map for atomicMax on floats.
__device__ __forceinline__ unsigned enc_f(float f) {
    unsigned u = __float_as_uint(f);
    return (u & 0x80000000u) ? ~u : (u | 0x80000000u);
}
__device__ __forceinline__ float dec_f(unsigned u) {
    return (u & 0x80000000u) ? __uint_as_float(u ^ 0x80000000u)
                             : __uint_as_float(~u);
}

__global__ void k_init_nodes() {
    int i = blockIdx.x * blockDim.x + threadIdx.x;
    if (i < Nn) {
        g_me[i] = 0u;   // enc(-inf) < enc(x) for all finite x; 0 is safe floor
        g_mw[i] = 0u;
        g_se[i] = 0.f;
        g_sw[i] = 0.f;
    }
}

__global__ void k_init_out(float* __restrict__ out, const float* __restrict__ bias) {
    int i = blockIdx.x * blockDim.x + threadIdx.x;
    if (i < Nn * OUTF) out[i] = bias[i & (OUTF - 1)];
}

// ---------------------------------------------------------------------------
// fp32 tiled GEMM: g_ft[N,128] = feat[N,256] @ fc_w[256,128]
// Block: 256 threads, tile 64(M) x 128(N), BK=32, per-thread 4x8 micro-tile.
// ---------------------------------------------------------------------------
__global__ __launch_bounds__(256) void k_gemm(const float* __restrict__ feat,
                                              const float* __restrict__ fcw) {
    __shared__ float As[32][64];    // k-major A tile (transposed on store)
    __shared__ float Bs[32][128];

    int tid = threadIdx.x;
    int tx = tid & 15;              // 16 col-groups of 8
    int ty = tid >> 4;              // 16 row-groups of 4
    int row0 = blockIdx.x * 64;

    float acc[4][8];
#pragma unroll
    for (int i = 0; i < 4; i++)
#pragma unroll
        for (int j = 0; j < 8; j++) acc[i][j] = 0.f;

    for (int kk = 0; kk < INF; kk += 32) {
        // Load A tile: 64 rows x 32 k  (512 float4, 2 per thread), transpose to k-major
#pragma unroll
        for (int j = 0; j < 2; j++) {
            int f = tid + 256 * j;
            int r = f >> 3;
            int c4 = f & 7;
            float4 v = make_float4(0.f, 0.f, 0.f, 0.f);
            if (row0 + r < Nn)
                v = *(const float4*)(feat + (size_t)(row0 + r) * INF + kk + c4 * 4);
            As[c4 * 4 + 0][r] = v.x;
            As[c4 * 4 + 1][r] = v.y;
            As[c4 * 4 + 2][r] = v.z;
            As[c4 * 4 + 3][r] = v.w;
        }
        // Load B tile: 32 k x 128 cols (1024 float4, 4 per thread)
#pragma unroll
        for (int j = 0; j < 4; j++) {
            int f = tid + 256 * j;
            int r = f >> 5;
            int c4 = f & 31;
            *(float4*)&Bs[r][c4 * 4] = *(const float4*)(fcw + (size_t)(kk + r) * OUTF + c4 * 4);
        }
        __syncthreads();

#pragma unroll
        for (int k = 0; k < 32; k++) {
            float a[4], b[8];
            *(float4*)a      = *(const float4*)&As[k][ty * 4];
            *(float4*)&b[0]  = *(const float4*)&Bs[k][tx * 8];
            *(float4*)&b[4]  = *(const float4*)&Bs[k][tx * 8 + 4];
#pragma unroll
            for (int i = 0; i < 4; i++)
#pragma unroll
                for (int j = 0; j < 8; j++)
                    acc[i][j] = fmaf(a[i], b[j], acc[i][j]);
        }
        __syncthreads();
    }

#pragma unroll
    for (int i = 0; i < 4; i++) {
        int r = row0 + ty * 4 + i;
        if (r < Nn) {
            *(float4*)(g_ft + (size_t)r * OUTF + tx * 8)     = *(float4*)&acc[i][0];
            *(float4*)(g_ft + (size_t)r * OUTF + tx * 8 + 4) = *(float4*)&acc[i][4];
        }
    }
}

// ---------------------------------------------------------------------------
// Per-node attention logits: el = ft . attn_l, er = ft . attn_r (warp/node)
// ---------------------------------------------------------------------------
__global__ void k_elr(const float* __restrict__ attn_l, const float* __restrict__ attn_r) {
    int warp = (blockIdx.x * blockDim.x + threadIdx.x) >> 5;
    int lane = threadIdx.x & 31;
    if (warp >= Nn) return;
    float4 f  = *(const float4*)(g_ft + (size_t)warp * OUTF + lane * 4);
    float4 al = *(const float4*)(attn_l + lane * 4);
    float4 ar = *(const float4*)(attn_r + lane * 4);
    float el = f.x * al.x + f.y * al.y + f.z * al.z + f.w * al.w;
    float er = f.x * ar.x + f.y * ar.y + f.z * ar.z + f.w * ar.w;
#pragma unroll
    for (int o = 16; o; o >>= 1) {
        el += __shfl_xor_sync(0xFFFFFFFFu, el, o);
        er += __shfl_xor_sync(0xFFFFFFFFu, er, o);
    }
    if (lane == 0) {
        g_el[warp] = el;
        g_er[warp] = er;
    }
}

// ---------------------------------------------------------------------------
// Edge pass 1: scores + segment max (atomicMax on ordered-uint encoding)
// ---------------------------------------------------------------------------
__global__ void k_edge_max(const float* __restrict__ w,
                           const int* __restrict__ src, const int* __restrict__ dst) {
    int i = blockIdx.x * blockDim.x + threadIdx.x;
    if (i >= Ee) return;
    int s = src[i], d = dst[i];
    float e = g_el[s] + g_er[d];
    e = e > 0.f ? e : NEG_SLOPE * e;
    g_e[i] = e;
    atomicMax(&g_me[d], enc_f(e));
    atomicMax(&g_mw[d], enc_f(w[i]));
}

// ---------------------------------------------------------------------------
// Edge pass 2: exp + segment sum
// ---------------------------------------------------------------------------
__global__ void k_edge_sum(const float* __restrict__ w, const int* __restrict__ dst) {
    int i = blockIdx.x * blockDim.x + threadIdx.x;
    if (i >= Ee) return;
    int d = dst[i];
    float z  = expf(g_e[i] - dec_f(g_me[d]));
    float zw = expf(w[i]   - dec_f(g_mw[d]));
    g_z[i]  = z;
    g_zw[i] = zw;
    atomicAdd(&g_se[d], z);
    atomicAdd(&g_sw[d], zw);
}

// ---------------------------------------------------------------------------
// Edge pass 3: blended attention * ft[src] -> atomic accumulate into out[dst]
// One warp per edge; lane handles 4 contiguous dims; vectorized RED.128.
// ---------------------------------------------------------------------------
__global__ __launch_bounds__(256) void k_agg(const int* __restrict__ src,
                                             const int* __restrict__ dst,
                                             float* __restrict__ out) {
    int e = (blockIdx.x * blockDim.x + threadIdx.x) >> 5;
    int lane = threadIdx.x & 31;
    if (e >= Ee) return;
    int s = src[e], d = dst[e];
    float a = (1.f - ALPHA) * g_z[e] / g_se[d] + ALPHA * g_zw[e] / g_sw[d];
    float4 v = *(const float4*)(g_ft + (size_t)s * OUTF + lane * 4);
    v.x *= a; v.y *= a; v.z *= a; v.w *= a;
    float* p = out + (size_t)d * OUTF + lane * 4;
    asm volatile("red.global.add.v4.f32 [%0], {%1,%2,%3,%4};"
                 :: "l"(p), "f"(v.x), "f"(v.y), "f"(v.z), "f"(v.w)
                 : "memory");
}

extern "C" void kernel_launch(void* const* d_in, const int* in_sizes, int n_in,
                              void* d_out, int out_size) {
    const float* feat   = (const float*)d_in[0];
    const float* w      = (const float*)d_in[1];
    const float* fcw    = (const float*)d_in[2];
    const float* attn_l = (const float*)d_in[3];
    const float* attn_r = (const float*)d_in[4];
    const float* bias   = (const float*)d_in[5];
    const int*   src    = (const int*)d_in[6];
    const int*   dst    = (const int*)d_in[7];
    float* out = (float*)d_out;

    k_init_nodes<<<(Nn + 255) / 256, 256>>>();
    k_init_out<<<(Nn * OUTF + 255) / 256, 256>>>(out, bias);
    k_gemm<<<(Nn + 63) / 64, 256>>>(feat, fcw);
    k_elr<<<((size_t)Nn * 32 + 255) / 256, 256>>>(attn_l, attn_r);
    k_edge_max<<<(Ee + 255) / 256, 256>>>(w, src, dst);
    k_edge_sum<<<(Ee + 255) / 256, 256>>>(w, dst);
    k_agg<<<((size_t)Ee * 32 + 255) / 256, 256>>>(src, dst, out);
}

// round 2
// speedup vs baseline: 1.0404x; 1.0404x over previous
#include <cuda_runtime.h>

#define Nn 50000
#define Ee 800000
#define INF 256
#define OUTF 128
#define NEG_SLOPE 0.2f
#define ALPHA 0.5f

// Scratch (static device globals; no runtime allocation)
__device__ float g_ft[(size_t)Nn * OUTF];   // fc projection [N,128]
__device__ float g_el[Nn];
__device__ float g_er[Nn];
__device__ float g_se[Nn];                  // segment sum exp(e)
__device__ float g_sw[Nn];                  // segment sum exp(w)
__device__ int   g_deg[Nn];                 // in-degree per node
__device__ int   g_off[Nn + 1];             // CSR offsets
__device__ int   g_cur[Nn];                 // scatter cursors
__device__ float g_z[Ee];                   // exp(e)
__device__ float g_zw[Ee];                  // exp(w)
__device__ int   g_srcs[Ee];                // src ids bucketed by dst
__device__ float g_as[Ee];                  // blended attention bucketed by dst

__global__ void k_init() {
    int i = blockIdx.x * blockDim.x + threadIdx.x;
    if (i < Nn) {
        g_se[i] = 0.f;
        g_sw[i] = 0.f;
        g_deg[i] = 0;
    }
}

// ---------------------------------------------------------------------------
// fp32 tiled GEMM: g_ft[N,128] = feat[N,256] @ fc_w[256,128]
// Block: 256 threads, tile 64(M) x 128(N), BK=32, per-thread 4x8 micro-tile.
// Fused epilogue: el/er attention logits via half-warp shfl reduction.
// ---------------------------------------------------------------------------
__global__ __launch_bounds__(256) void k_gemm(const float* __restrict__ feat,
                                              const float* __restrict__ fcw,
                                              const float* __restrict__ attn_l,
                                              const float* __restrict__ attn_r) {
    __shared__ float As[32][64];    // k-major A tile (transposed on store)
    __shared__ float Bs[32][128];

    int tid = threadIdx.x;
    int tx = tid & 15;              // 16 col-groups of 8
    int ty = tid >> 4;              // 16 row-groups of 4
    int row0 = blockIdx.x * 64;

    float acc[4][8];
#pragma unroll
    for (int i = 0; i < 4; i++)
#pragma unroll
        for (int j = 0; j < 8; j++) acc[i][j] = 0.f;

    for (int kk = 0; kk < INF; kk += 32) {
        // Load A tile: 64 rows x 32 k, transpose to k-major
#pragma unroll
        for (int j = 0; j < 2; j++) {
            int f = tid + 256 * j;
            int r = f >> 3;
            int c4 = f & 7;
            float4 v = make_float4(0.f, 0.f, 0.f, 0.f);
            if (row0 + r < Nn)
                v = *(const float4*)(feat + (size_t)(row0 + r) * INF + kk + c4 * 4);
            As[c4 * 4 + 0][r] = v.x;
            As[c4 * 4 + 1][r] = v.y;
            As[c4 * 4 + 2][r] = v.z;
            As[c4 * 4 + 3][r] = v.w;
        }
        // Load B tile: 32 k x 128 cols
#pragma unroll
        for (int j = 0; j < 4; j++) {
            int f = tid + 256 * j;
            int r = f >> 5;
            int c4 = f & 31;
            *(float4*)&Bs[r][c4 * 4] = *(const float4*)(fcw + (size_t)(kk + r) * OUTF + c4 * 4);
        }
        __syncthreads();

#pragma unroll
        for (int k = 0; k < 32; k++) {
            float a[4], b[8];
            *(float4*)a     = *(const float4*)&As[k][ty * 4];
            *(float4*)&b[0] = *(const float4*)&Bs[k][tx * 8];
            *(float4*)&b[4] = *(const float4*)&Bs[k][tx * 8 + 4];
#pragma unroll
            for (int i = 0; i < 4; i++)
#pragma unroll
                for (int j = 0; j < 8; j++)
                    acc[i][j] = fmaf(a[i], b[j], acc[i][j]);
        }
        __syncthreads();
    }

    // Load attention vectors for this thread's 8 columns
    float al[8], ar[8];
    *(float4*)&al[0] = *(const float4*)(attn_l + tx * 8);
    *(float4*)&al[4] = *(const float4*)(attn_l + tx * 8 + 4);
    *(float4*)&ar[0] = *(const float4*)(attn_r + tx * 8);
    *(float4*)&ar[4] = *(const float4*)(attn_r + tx * 8 + 4);

#pragma unroll
    for (int i = 0; i < 4; i++) {
        int r = row0 + ty * 4 + i;
        if (r < Nn) {
            *(float4*)(g_ft + (size_t)r * OUTF + tx * 8)     = *(float4*)&acc[i][0];
            *(float4*)(g_ft + (size_t)r * OUTF + tx * 8 + 4) = *(float4*)&acc[i][4];
        }
        // partial dots for el/er
        float pl = 0.f, pr = 0.f;
#pragma unroll
        for (int j = 0; j < 8; j++) {
            pl = fmaf(acc[i][j], al[j], pl);
            pr = fmaf(acc[i][j], ar[j], pr);
        }
        // reduce over the 16 tx lanes (tx occupies low 4 bits of lane id)
#pragma unroll
        for (int o = 8; o; o >>= 1) {
            pl += __shfl_xor_sync(0xFFFFFFFFu, pl, o);
            pr += __shfl_xor_sync(0xFFFFFFFFu, pr, o);
        }
        if (tx == 0 && r < Nn) {
            g_el[r] = pl;
            g_er[r] = pr;
        }
    }
}

// ---------------------------------------------------------------------------
// Edge pass: leaky-relu score, exp (no max shift: |logit| < ~10, safe),
// segment sums + degree histogram.
// ---------------------------------------------------------------------------
__global__ void k_edge(const float* __restrict__ w,
                       const int* __restrict__ src, const int* __restrict__ dst) {
    int i = blockIdx.x * blockDim.x + threadIdx.x;
    if (i >= Ee) return;
    int s = src[i], d = dst[i];
    float e = g_el[s] + g_er[d];
    e = e > 0.f ? e : NEG_SLOPE * e;
    float z  = expf(e);
    float zw = expf(w[i]);
    g_z[i]  = z;
    g_zw[i] = zw;
    atomicAdd(&g_se[d], z);
    atomicAdd(&g_sw[d], zw);
    atomicAdd(&g_deg[d], 1);
}

// ---------------------------------------------------------------------------
// Single-block exclusive prefix scan of degrees -> CSR offsets + cursors.
// ---------------------------------------------------------------------------
#define SCAN_T 1024
#define CHUNK ((Nn + SCAN_T - 1) / SCAN_T)
__global__ __launch_bounds__(SCAN_T) void k_scan() {
    __shared__ int sums[SCAN_T];
    int t = threadIdx.x;
    int start = t * CHUNK;
    int end = min(start + CHUNK, Nn);
    int s = 0;
    for (int i = start; i < end; i++) s += g_deg[i];
    sums[t] = s;
    __syncthreads();
    // Hillis-Steele inclusive scan
    for (int o = 1; o < SCAN_T; o <<= 1) {
        int v = (t >= o) ? sums[t - o] : 0;
        __syncthreads();
        sums[t] += v;
        __syncthreads();
    }
    int run = sums[t] - s;  // exclusive prefix for this chunk
    for (int i = start; i < end; i++) {
        g_off[i] = run;
        g_cur[i] = run;
        run += g_deg[i];
    }
    if (t == 0) g_off[Nn] = Ee;
}

// ---------------------------------------------------------------------------
// Scatter: bucket (src, blended-attention) by dst.
// ---------------------------------------------------------------------------
__global__ void k_scatter(const int* __restrict__ src, const int* __restrict__ dst) {
    int i = blockIdx.x * blockDim.x + threadIdx.x;
    if (i >= Ee) return;
    int d = dst[i];
    float a = (1.f - ALPHA) * g_z[i] / g_se[d] + ALPHA * g_zw[i] / g_sw[d];
    int pos = atomicAdd(&g_cur[d], 1);
    g_srcs[pos] = src[i];
    g_as[pos]   = a;
}

// ---------------------------------------------------------------------------
// CSR aggregation: one warp per dst node, accumulate in registers, one store.
// ---------------------------------------------------------------------------
__global__ __launch_bounds__(256) void k_agg_csr(const float* __restrict__ bias,
                                                 float* __restrict__ out) {
    int node = blockIdx.x * 8 + (threadIdx.x >> 5);
    int lane = threadIdx.x & 31;
    if (node >= Nn) return;
    int beg = g_off[node], end = g_off[node + 1];

    float4 acc = *(const float4*)(bias + lane * 4);

    for (int base = beg; base < end; base += 32) {
        int n = min(32, end - base);
        int s = 0;
        float a = 0.f;
        if (lane < n) {
            s = g_srcs[base + lane];
            a = g_as[base + lane];
        }
        for (int j = 0; j < n; j++) {
            int   sj = __shfl_sync(0xFFFFFFFFu, s, j);
            float aj = __shfl_sync(0xFFFFFFFFu, a, j);
            float4 v = *(const float4*)(g_ft + (size_t)sj * OUTF + lane * 4);
            acc.x = fmaf(aj, v.x, acc.x);
            acc.y = fmaf(aj, v.y, acc.y);
            acc.z = fmaf(aj, v.z, acc.z);
            acc.w = fmaf(aj, v.w, acc.w);
        }
    }
    *(float4*)(out + (size_t)node * OUTF + lane * 4) = acc;
}

extern "C" void kernel_launch(void* const* d_in, const int* in_sizes, int n_in,
                              void* d_out, int out_size) {
    const float* feat   = (const float*)d_in[0];
    const float* w      = (const float*)d_in[1];
    const float* fcw    = (const float*)d_in[2];
    const float* attn_l = (const float*)d_in[3];
    const float* attn_r = (const float*)d_in[4];
    const float* bias   = (const float*)d_in[5];
    const int*   src    = (const int*)d_in[6];
    const int*   dst    = (const int*)d_in[7];
    float* out = (float*)d_out;

    k_init<<<(Nn + 255) / 256, 256>>>();
    k_gemm<<<(Nn + 63) / 64, 256>>>(feat, fcw, attn_l, attn_r);
    k_edge<<<(Ee + 255) / 256, 256>>>(w, src, dst);
    k_scan<<<1, SCAN_T>>>();
    k_scatter<<<(Ee + 255) / 256, 256>>>(src, dst);
    k_agg_csr<<<(Nn + 7) / 8, 256>>>(bias, out);
}

// round 3
// speedup vs baseline: 1.3826x; 1.3290x over previous
#include <cuda_runtime.h>

#define Nn 50000
#define Ee 800000
#define INF 256
#define OUTF 128
#define NEG_SLOPE 0.2f
#define ALPHA 0.5f

#define SCAN_T 256
#define SCAN_BLOCKS ((Nn + SCAN_T - 1) / SCAN_T)   // 196

// Scratch (static device globals; no runtime allocation)
__device__ float g_ft[(size_t)Nn * OUTF];   // fc projection [N,128]
__device__ float g_el[Nn];
__device__ float g_er[Nn];
__device__ float g_se[Nn];                  // segment sum exp(e)
__device__ float g_sw[Nn];                  // segment sum exp(w)
__device__ int   g_deg[Nn];                 // in-degree per node
__device__ int   g_off[Nn + 1];             // CSR offsets
__device__ int   g_cur[Nn];                 // scatter cursors
__device__ int   g_blk[SCAN_BLOCKS];        // per-block degree totals
__device__ float g_z[Ee];                   // exp(e)
__device__ float g_zw[Ee];                  // exp(w)
__device__ int   g_srcs[Ee];                // src ids bucketed by dst
__device__ float g_as[Ee];                  // blended attention bucketed by dst

__global__ void k_init() {
    int i = blockIdx.x * blockDim.x + threadIdx.x;
    if (i < Nn) {
        g_se[i] = 0.f;
        g_sw[i] = 0.f;
        g_deg[i] = 0;
    }
}

// ---------------------------------------------------------------------------
// fp32 tiled GEMM: g_ft[N,128] = feat[N,256] @ fc_w[256,128]
// Block: 256 threads, tile 64(M) x 128(N), BK=32, per-thread 4x8 micro-tile.
// Fused epilogue: el/er attention logits via half-warp shfl reduction.
// ---------------------------------------------------------------------------
__global__ __launch_bounds__(256) void k_gemm(const float* __restrict__ feat,
                                              const float* __restrict__ fcw,
                                              const float* __restrict__ attn_l,
                                              const float* __restrict__ attn_r) {
    __shared__ float As[32][64];    // k-major A tile (transposed on store)
    __shared__ float Bs[32][128];

    int tid = threadIdx.x;
    int tx = tid & 15;              // 16 col-groups of 8
    int ty = tid >> 4;              // 16 row-groups of 4
    int row0 = blockIdx.x * 64;

    float acc[4][8];
#pragma unroll
    for (int i = 0; i < 4; i++)
#pragma unroll
        for (int j = 0; j < 8; j++) acc[i][j] = 0.f;

    for (int kk = 0; kk < INF; kk += 32) {
        // Load A tile: 64 rows x 32 k, transpose to k-major
#pragma unroll
        for (int j = 0; j < 2; j++) {
            int f = tid + 256 * j;
            int r = f >> 3;
            int c4 = f & 7;
            float4 v = make_float4(0.f, 0.f, 0.f, 0.f);
            if (row0 + r < Nn)
                v = *(const float4*)(feat + (size_t)(row0 + r) * INF + kk + c4 * 4);
            As[c4 * 4 + 0][r] = v.x;
            As[c4 * 4 + 1][r] = v.y;
            As[c4 * 4 + 2][r] = v.z;
            As[c4 * 4 + 3][r] = v.w;
        }
        // Load B tile: 32 k x 128 cols
#pragma unroll
        for (int j = 0; j < 4; j++) {
            int f = tid + 256 * j;
            int r = f >> 5;
            int c4 = f & 31;
            *(float4*)&Bs[r][c4 * 4] = *(const float4*)(fcw + (size_t)(kk + r) * OUTF + c4 * 4);
        }
        __syncthreads();

#pragma unroll
        for (int k = 0; k < 32; k++) {
            float a[4], b[8];
            *(float4*)a     = *(const float4*)&As[k][ty * 4];
            *(float4*)&b[0] = *(const float4*)&Bs[k][tx * 8];
            *(float4*)&b[4] = *(const float4*)&Bs[k][tx * 8 + 4];
#pragma unroll
            for (int i = 0; i < 4; i++)
#pragma unroll
                for (int j = 0; j < 8; j++)
                    acc[i][j] = fmaf(a[i], b[j], acc[i][j]);
        }
        __syncthreads();
    }

    // Load attention vectors for this thread's 8 columns
    float al[8], ar[8];
    *(float4*)&al[0] = *(const float4*)(attn_l + tx * 8);
    *(float4*)&al[4] = *(const float4*)(attn_l + tx * 8 + 4);
    *(float4*)&ar[0] = *(const float4*)(attn_r + tx * 8);
    *(float4*)&ar[4] = *(const float4*)(attn_r + tx * 8 + 4);

#pragma unroll
    for (int i = 0; i < 4; i++) {
        int r = row0 + ty * 4 + i;
        if (r < Nn) {
            *(float4*)(g_ft + (size_t)r * OUTF + tx * 8)     = *(float4*)&acc[i][0];
            *(float4*)(g_ft + (size_t)r * OUTF + tx * 8 + 4) = *(float4*)&acc[i][4];
        }
        // partial dots for el/er
        float pl = 0.f, pr = 0.f;
#pragma unroll
        for (int j = 0; j < 8; j++) {
            pl = fmaf(acc[i][j], al[j], pl);
            pr = fmaf(acc[i][j], ar[j], pr);
        }
        // reduce over the 16 tx lanes (tx occupies low 4 bits of lane id)
#pragma unroll
        for (int o = 8; o; o >>= 1) {
            pl += __shfl_xor_sync(0xFFFFFFFFu, pl, o);
            pr += __shfl_xor_sync(0xFFFFFFFFu, pr, o);
        }
        if (tx == 0 && r < Nn) {
            g_el[r] = pl;
            g_er[r] = pr;
        }
    }
}

// ---------------------------------------------------------------------------
// Edge pass: leaky-relu score, exp (no max shift: |logit| < ~10, safe),
// segment sums + degree histogram.
// ---------------------------------------------------------------------------
__global__ void k_edge(const float* __restrict__ w,
                       const int* __restrict__ src, const int* __restrict__ dst) {
    int i = blockIdx.x * blockDim.x + threadIdx.x;
    if (i >= Ee) return;
    int s = src[i], d = dst[i];
    float e = g_el[s] + g_er[d];
    e = e > 0.f ? e : NEG_SLOPE * e;
    float z  = expf(e);
    float zw = expf(w[i]);
    g_z[i]  = z;
    g_zw[i] = zw;
    atomicAdd(&g_se[d], z);
    atomicAdd(&g_sw[d], zw);
    atomicAdd(&g_deg[d], 1);
}

// ---------------------------------------------------------------------------
// Three-phase parallel prefix scan of degrees -> CSR offsets + cursors.
// ---------------------------------------------------------------------------
__global__ __launch_bounds__(SCAN_T) void k_scan_a() {
    __shared__ int sh[SCAN_T];
    int t = threadIdx.x;
    int i = blockIdx.x * SCAN_T + t;
    int d = (i < Nn) ? g_deg[i] : 0;
    sh[t] = d;
    __syncthreads();
    // Hillis-Steele inclusive scan
#pragma unroll
    for (int o = 1; o < SCAN_T; o <<= 1) {
        int v = (t >= o) ? sh[t - o] : 0;
        __syncthreads();
        sh[t] += v;
        __syncthreads();
    }
    if (i < Nn) g_off[i] = sh[t] - d;           // within-block exclusive
    if (t == SCAN_T - 1) g_blk[blockIdx.x] = sh[t];  // block total
}

__global__ __launch_bounds__(SCAN_T) void k_scan_b() {
    __shared__ int sh[SCAN_T];
    int t = threadIdx.x;
    int d = (t < SCAN_BLOCKS) ? g_blk[t] : 0;
    sh[t] = d;
    __syncthreads();
#pragma unroll
    for (int o = 1; o < SCAN_T; o <<= 1) {
        int v = (t >= o) ? sh[t - o] : 0;
        __syncthreads();
        sh[t] += v;
        __syncthreads();
    }
    if (t < SCAN_BLOCKS) g_blk[t] = sh[t] - d;  // exclusive block prefix
}

__global__ __launch_bounds__(SCAN_T) void k_scan_c() {
    int i = blockIdx.x * SCAN_T + threadIdx.x;
    if (i < Nn) {
        int v = g_off[i] + g_blk[blockIdx.x];
        g_off[i] = v;
        g_cur[i] = v;
    }
    if (i == 0) g_off[Nn] = Ee;
}

// ---------------------------------------------------------------------------
// Scatter: bucket (src, blended-attention) by dst.
// ---------------------------------------------------------------------------
__global__ void k_scatter(const int* __restrict__ src, const int* __restrict__ dst) {
    int i = blockIdx.x * blockDim.x + threadIdx.x;
    if (i >= Ee) return;
    int d = dst[i];
    float a = (1.f - ALPHA) * g_z[i] / g_se[d] + ALPHA * g_zw[i] / g_sw[d];
    int pos = atomicAdd(&g_cur[d], 1);
    g_srcs[pos] = src[i];
    g_as[pos]   = a;
}

// ---------------------------------------------------------------------------
// CSR aggregation: one warp per dst node, accumulate in registers, one store.
// ---------------------------------------------------------------------------
__global__ __launch_bounds__(256) void k_agg_csr(const float* __restrict__ bias,
                                                 float* __restrict__ out) {
    int node = blockIdx.x * 8 + (threadIdx.x >> 5);
    int lane = threadIdx.x & 31;
    if (node >= Nn) return;
    int beg = g_off[node], end = g_off[node + 1];

    float4 acc = *(const float4*)(bias + lane * 4);

    for (int base = beg; base < end; base += 32) {
        int n = min(32, end - base);
        int s = 0;
        float a = 0.f;
        if (lane < n) {
            s = g_srcs[base + lane];
            a = g_as[base + lane];
        }
        for (int j = 0; j < n; j++) {
            int   sj = __shfl_sync(0xFFFFFFFFu, s, j);
            float aj = __shfl_sync(0xFFFFFFFFu, a, j);
            float4 v = *(const float4*)(g_ft + (size_t)sj * OUTF + lane * 4);
            acc.x = fmaf(aj, v.x, acc.x);
            acc.y = fmaf(aj, v.y, acc.y);
            acc.z = fmaf(aj, v.z, acc.z);
            acc.w = fmaf(aj, v.w, acc.w);
        }
    }
    *(float4*)(out + (size_t)node * OUTF + lane * 4) = acc;
}

extern "C" void kernel_launch(void* const* d_in, const int* in_sizes, int n_in,
                              void* d_out, int out_size) {
    const float* feat   = (const float*)d_in[0];
    const float* w      = (const float*)d_in[1];
    const float* fcw    = (const float*)d_in[2];
    const float* attn_l = (const float*)d_in[3];
    const float* attn_r = (const float*)d_in[4];
    const float* bias   = (const float*)d_in[5];
    const int*   src    = (const int*)d_in[6];
    const int*   dst    = (const int*)d_in[7];
    float* out = (float*)d_out;

    k_init<<<(Nn + 255) / 256, 256>>>();
    k_gemm<<<(Nn + 63) / 64, 256>>>(feat, fcw, attn_l, attn_r);
    k_edge<<<(Ee + 255) / 256, 256>>>(w, src, dst);
    k_scan_a<<<SCAN_BLOCKS, SCAN_T>>>();
    k_scan_b<<<1, SCAN_T>>>();
    k_scan_c<<<SCAN_BLOCKS, SCAN_T>>>();
    k_scatter<<<(Ee + 255) / 256, 256>>>(src, dst);
    k_agg_csr<<<(Nn + 7) / 8, 256>>>(bias, out);
}

// round 4
// speedup vs baseline: 1.3867x; 1.0029x over previous
#include <cuda_runtime.h>

#define Nn 50000
#define Ee 800000
#define INF 256
#define OUTF 128
#define NEG_SLOPE 0.2f
#define ALPHA 0.5f

#define SCAN_T 256
#define SCAN_BLOCKS ((Nn + SCAN_T - 1) / SCAN_T)   // 196

// Scratch (static device globals; no runtime allocation)
__device__ float g_ft[(size_t)Nn * OUTF];   // fc projection [N,128]
__device__ float g_el[Nn];
__device__ float g_er[Nn];
__device__ float g_se[Nn];                  // segment sum exp(e)
__device__ float g_sw[Nn];                  // segment sum exp(w)
__device__ int   g_deg[Nn];                 // in-degree per node
__device__ int   g_off[Nn + 1];             // CSR offsets
__device__ int   g_cur[Nn];                 // scatter cursors
__device__ int   g_blk[SCAN_BLOCKS];        // per-block degree totals
__device__ float g_z[Ee];                   // exp(e)
__device__ float g_zw[Ee];                  // exp(w)
__device__ int   g_srcs[Ee];                // src ids bucketed by dst
__device__ float g_as[Ee];                  // blended attention bucketed by dst

__global__ void k_init() {
    int i = blockIdx.x * blockDim.x + threadIdx.x;
    if (i < Nn) {
        g_se[i] = 0.f;
        g_sw[i] = 0.f;
        g_deg[i] = 0;
    }
}

// Packed f32x2 helpers (sm_103a FFMA2 — only reachable via PTX)
__device__ __forceinline__ unsigned long long pack2(float lo, float hi) {
    unsigned long long r;
    asm("mov.b64 %0, {%1, %2};" : "=l"(r) : "f"(lo), "f"(hi));
    return r;
}
__device__ __forceinline__ void ffma2(unsigned long long& d,
                                      unsigned long long a,
                                      unsigned long long b) {
    asm("fma.rn.f32x2 %0, %1, %2, %3;" : "=l"(d) : "l"(a), "l"(b), "l"(d));
}

// ---------------------------------------------------------------------------
// fp32 tiled GEMM with packed FFMA2: g_ft[N,128] = feat[N,256] @ fc_w[256,128]
// Block: 256 threads, tile 64(M) x 128(N), BK=32, per-thread 4x8 micro-tile
// held as 4x4 f32x2 pairs. Fused epilogue: el/er logits.
// ---------------------------------------------------------------------------
__global__ __launch_bounds__(256) void k_gemm(const float* __restrict__ feat,
                                              const float* __restrict__ fcw,
                                              const float* __restrict__ attn_l,
                                              const float* __restrict__ attn_r) {
    __shared__ float As[32][64];    // k-major A tile (transposed on store)
    __shared__ float Bs[32][128];

    int tid = threadIdx.x;
    int tx = tid & 15;              // 16 col-groups of 8
    int ty = tid >> 4;              // 16 row-groups of 4
    int row0 = blockIdx.x * 64;

    unsigned long long acc2[4][4];  // [mi][pair]: pair p = cols (2p, 2p+1)
#pragma unroll
    for (int i = 0; i < 4; i++)
#pragma unroll
        for (int j = 0; j < 4; j++) acc2[i][j] = 0ull;

    for (int kk = 0; kk < INF; kk += 32) {
        // Load A tile: 64 rows x 32 k, transpose to k-major
#pragma unroll
        for (int j = 0; j < 2; j++) {
            int f = tid + 256 * j;
            int r = f >> 3;
            int c4 = f & 7;
            float4 v = make_float4(0.f, 0.f, 0.f, 0.f);
            if (row0 + r < Nn)
                v = *(const float4*)(feat + (size_t)(row0 + r) * INF + kk + c4 * 4);
            As[c4 * 4 + 0][r] = v.x;
            As[c4 * 4 + 1][r] = v.y;
            As[c4 * 4 + 2][r] = v.z;
            As[c4 * 4 + 3][r] = v.w;
        }
        // Load B tile: 32 k x 128 cols
#pragma unroll
        for (int j = 0; j < 4; j++) {
            int f = tid + 256 * j;
            int r = f >> 5;
            int c4 = f & 31;
            *(float4*)&Bs[r][c4 * 4] = *(const float4*)(fcw + (size_t)(kk + r) * OUTF + c4 * 4);
        }
        __syncthreads();

#pragma unroll
        for (int k = 0; k < 32; k++) {
            float a[4];
            *(float4*)a = *(const float4*)&As[k][ty * 4];
            unsigned long long b2[4];
            const unsigned long long* bp = (const unsigned long long*)&Bs[k][tx * 8];
#pragma unroll
            for (int j = 0; j < 4; j++) b2[j] = bp[j];
            unsigned long long a2[4];
#pragma unroll
            for (int i = 0; i < 4; i++) a2[i] = pack2(a[i], a[i]);
#pragma unroll
            for (int i = 0; i < 4; i++)
#pragma unroll
                for (int j = 0; j < 4; j++)
                    ffma2(acc2[i][j], a2[i], b2[j]);
        }
        __syncthreads();
    }

    // Load attention vectors for this thread's 8 columns
    float al[8], ar[8];
    *(float4*)&al[0] = *(const float4*)(attn_l + tx * 8);
    *(float4*)&al[4] = *(const float4*)(attn_l + tx * 8 + 4);
    *(float4*)&ar[0] = *(const float4*)(attn_r + tx * 8);
    *(float4*)&ar[4] = *(const float4*)(attn_r + tx * 8 + 4);

#pragma unroll
    for (int i = 0; i < 4; i++) {
        const float* accf = (const float*)&acc2[i][0];   // 8 consecutive cols
        int r = row0 + ty * 4 + i;
        if (r < Nn) {
            *(float4*)(g_ft + (size_t)r * OUTF + tx * 8)     = *(const float4*)&accf[0];
            *(float4*)(g_ft + (size_t)r * OUTF + tx * 8 + 4) = *(const float4*)&accf[4];
        }
        // partial dots for el/er
        float pl = 0.f, pr = 0.f;
#pragma unroll
        for (int j = 0; j < 8; j++) {
            pl = fmaf(accf[j], al[j], pl);
            pr = fmaf(accf[j], ar[j], pr);
        }
        // reduce over the 16 tx lanes (tx occupies low 4 bits of lane id)
#pragma unroll
        for (int o = 8; o; o >>= 1) {
            pl += __shfl_xor_sync(0xFFFFFFFFu, pl, o);
            pr += __shfl_xor_sync(0xFFFFFFFFu, pr, o);
        }
        if (tx == 0 && r < Nn) {
            g_el[r] = pl;
            g_er[r] = pr;
        }
    }
}

// ---------------------------------------------------------------------------
// Edge pass: leaky-relu score, exp (no max shift: |logit| < ~10, safe),
// segment sums + degree histogram.
// ---------------------------------------------------------------------------
__global__ void k_edge(const float* __restrict__ w,
                       const int* __restrict__ src, const int* __restrict__ dst) {
    int i = blockIdx.x * blockDim.x + threadIdx.x;
    if (i >= Ee) return;
    int s = src[i], d = dst[i];
    float e = g_el[s] + g_er[d];
    e = e > 0.f ? e : NEG_SLOPE * e;
    float z  = expf(e);
    float zw = expf(w[i]);
    g_z[i]  = z;
    g_zw[i] = zw;
    atomicAdd(&g_se[d], z);
    atomicAdd(&g_sw[d], zw);
    atomicAdd(&g_deg[d], 1);
}

// ---------------------------------------------------------------------------
// Three-phase parallel prefix scan of degrees -> CSR offsets + cursors.
// ---------------------------------------------------------------------------
__global__ __launch_bounds__(SCAN_T) void k_scan_a() {
    __shared__ int sh[SCAN_T];
    int t = threadIdx.x;
    int i = blockIdx.x * SCAN_T + t;
    int d = (i < Nn) ? g_deg[i] : 0;
    sh[t] = d;
    __syncthreads();
#pragma unroll
    for (int o = 1; o < SCAN_T; o <<= 1) {
        int v = (t >= o) ? sh[t - o] : 0;
        __syncthreads();
        sh[t] += v;
        __syncthreads();
    }
    if (i < Nn) g_off[i] = sh[t] - d;                 // within-block exclusive
    if (t == SCAN_T - 1) g_blk[blockIdx.x] = sh[t];   // block total
}

__global__ __launch_bounds__(SCAN_T) void k_scan_b() {
    __shared__ int sh[SCAN_T];
    int t = threadIdx.x;
    int d = (t < SCAN_BLOCKS) ? g_blk[t] : 0;
    sh[t] = d;
    __syncthreads();
#pragma unroll
    for (int o = 1; o < SCAN_T; o <<= 1) {
        int v = (t >= o) ? sh[t - o] : 0;
        __syncthreads();
        sh[t] += v;
        __syncthreads();
    }
    if (t < SCAN_BLOCKS) g_blk[t] = sh[t] - d;  // exclusive block prefix
}

__global__ __launch_bounds__(SCAN_T) void k_scan_c() {
    int i = blockIdx.x * SCAN_T + threadIdx.x;
    if (i < Nn) {
        int v = g_off[i] + g_blk[blockIdx.x];
        g_off[i] = v;
        g_cur[i] = v;
    }
    if (i == 0) g_off[Nn] = Ee;
}

// ---------------------------------------------------------------------------
// Scatter: bucket (src, blended-attention) by dst.
// ---------------------------------------------------------------------------
__global__ void k_scatter(const int* __restrict__ src, const int* __restrict__ dst) {
    int i = blockIdx.x * blockDim.x + threadIdx.x;
    if (i >= Ee) return;
    int d = dst[i];
    float a = (1.f - ALPHA) * g_z[i] / g_se[d] + ALPHA * g_zw[i] / g_sw[d];
    int pos = atomicAdd(&g_cur[d], 1);
    g_srcs[pos] = src[i];
    g_as[pos]   = a;
}

// ---------------------------------------------------------------------------
// CSR aggregation: one warp per dst node, accumulate in registers, one store.
// ---------------------------------------------------------------------------
__global__ __launch_bounds__(256) void k_agg_csr(const float* __restrict__ bias,
                                                 float* __restrict__ out) {
    int node = blockIdx.x * 8 + (threadIdx.x >> 5);
    int lane = threadIdx.x & 31;
    if (node >= Nn) return;
    int beg = g_off[node], end = g_off[node + 1];

    float4 acc = *(const float4*)(bias + lane * 4);

    for (int base = beg; base < end; base += 32) {
        int n = min(32, end - base);
        int s = 0;
        float a = 0.f;
        if (lane < n) {
            s = g_srcs[base + lane];
            a = g_as[base + lane];
        }
        for (int j = 0; j < n; j++) {
            int   sj = __shfl_sync(0xFFFFFFFFu, s, j);
            float aj = __shfl_sync(0xFFFFFFFFu, a, j);
            float4 v = *(const float4*)(g_ft + (size_t)sj * OUTF + lane * 4);
            acc.x = fmaf(aj, v.x, acc.x);
            acc.y = fmaf(aj, v.y, acc.y);
            acc.z = fmaf(aj, v.z, acc.z);
            acc.w = fmaf(aj, v.w, acc.w);
        }
    }
    *(float4*)(out + (size_t)node * OUTF + lane * 4) = acc;
}

extern "C" void kernel_launch(void* const* d_in, const int* in_sizes, int n_in,
                              void* d_out, int out_size) {
    const float* feat   = (const float*)d_in[0];
    const float* w      = (const float*)d_in[1];
    const float* fcw    = (const float*)d_in[2];
    const float* attn_l = (const float*)d_in[3];
    const float* attn_r = (const float*)d_in[4];
    const float* bias   = (const float*)d_in[5];
    const int*   src    = (const int*)d_in[6];
    const int*   dst    = (const int*)d_in[7];
    float* out = (float*)d_out;

    k_init<<<(Nn + 255) / 256, 256>>>();
    k_gemm<<<(Nn + 63) / 64, 256>>>(feat, fcw, attn_l, attn_r);
    k_edge<<<(Ee + 255) / 256, 256>>>(w, src, dst);
    k_scan_a<<<SCAN_BLOCKS, SCAN_T>>>();
    k_scan_b<<<1, SCAN_T>>>();
    k_scan_c<<<SCAN_BLOCKS, SCAN_T>>>();
    k_scatter<<<(Ee + 255) / 256, 256>>>(src, dst);
    k_agg_csr<<<(Nn + 7) / 8, 256>>>(bias, out);
}

// round 6
// speedup vs baseline: 2.1504x; 1.5507x over previous
#include <cuda_runtime.h>
#include <cuda_bf16.h>
#include <cstdint>

#define Nn 50000
#define Ee 800000
#define INF 256
#define OUTF 128
#define NEG_SLOPE 0.2f
#define ALPHA 0.5f

#define SCAN_T 256
#define SCAN_BLOCKS ((Nn + SCAN_T - 1) / SCAN_T)   // 196

// Scratch (static device globals; no runtime allocation)
__device__ float g_ft[(size_t)Nn * OUTF];   // fc projection [N,128]
__device__ float g_el[Nn];
__device__ float g_er[Nn];
__device__ float g_se[Nn];                  // segment sum exp(e)
__device__ float g_sw[Nn];                  // segment sum exp(w)
__device__ int   g_deg[Nn];                 // in-degree per node
__device__ int   g_off[Nn + 1];             // CSR offsets
__device__ int   g_cur[Nn];                 // scatter cursors
__device__ int   g_blk[SCAN_BLOCKS];        // per-block degree totals
__device__ float g_z[Ee];                   // exp(e)
__device__ float g_zw[Ee];                  // exp(w)
__device__ int   g_srcs[Ee];                // src ids bucketed by dst
__device__ float g_as[Ee];                  // blended attention bucketed by dst
// bf16 split of fc_w, transposed to [n][k]
__device__ __nv_bfloat16 g_bhi[OUTF * INF];
__device__ __nv_bfloat16 g_blo[OUTF * INF];

__device__ __forceinline__ uint32_t smem_u32(const void* p) {
    uint32_t a;
    asm("{ .reg .u64 t; cvta.to.shared.u64 t, %1; cvt.u32.u64 %0, t; }"
        : "=r"(a) : "l"(p));
    return a;
}

#define LDMATRIX_X4(q0, q1, q2, q3, addr) \
    asm volatile("ldmatrix.sync.aligned.m8n8.x4.shared.b16 {%0,%1,%2,%3}, [%4];" \
                 : "=r"(q0), "=r"(q1), "=r"(q2), "=r"(q3) : "r"(addr))

#define MMA16816(d, a0, a1, a2, a3, b0, b1) \
    asm volatile("mma.sync.aligned.m16n8k16.row.col.f32.bf16.bf16.f32 " \
                 "{%0,%1,%2,%3}, {%4,%5,%6,%7}, {%8,%9}, {%0,%1,%2,%3};" \
                 : "+f"((d)[0]), "+f"((d)[1]), "+f"((d)[2]), "+f"((d)[3]) \
                 : "r"(a0), "r"(a1), "r"(a2), "r"(a3), "r"(b0), "r"(b1))

__global__ void k_init_a() {
    int i = blockIdx.x * blockDim.x + threadIdx.x;
    if (i < Nn) {
        g_se[i] = 0.f;
        g_sw[i] = 0.f;
    }
}
__global__ void k_init_b() {
    int i = blockIdx.x * blockDim.x + threadIdx.x;
    if (i < Nn) g_deg[i] = 0;
}

// ---------------------------------------------------------------------------
// B split: g_bhi/g_blo[n][k] = bf16 hi/lo of fc_w[k][n]  (transpose, tiny)
// ---------------------------------------------------------------------------
__global__ void k_bsplit(const float* __restrict__ fcw) {
    int idx = blockIdx.x * blockDim.x + threadIdx.x;
    if (idx >= INF * OUTF) return;
    int k = idx >> 7, n = idx & 127;
    float v = fcw[idx];
    __nv_bfloat16 h = __float2bfloat16(v);
    __nv_bfloat16 l = __float2bfloat16(v - __bfloat162float(h));
    g_bhi[n * INF + k] = h;
    g_blo[n * INF + k] = l;
}

// ---------------------------------------------------------------------------
// Tensor-core GEMM (mma.sync bf16, 3-term split): g_ft = feat @ fc_w, fp32 acc.
// Block: 256 threads = 8 warps; tile M=128, N=128, K chunks of 32.
// Warp w computes rows [w*16, w*16+16) x all 128 cols: 16 n8-tiles, 64 acc regs.
// fp32 -> bf16 hi/lo split done in-kernel (feat read once).
// Fused epilogue: g_ft store + el/er dot products.
// ---------------------------------------------------------------------------
#define STR 40   // smem row stride in bf16 (32 data + 8 pad -> conflict-free ldmatrix)

__global__ __launch_bounds__(256) void k_gemm(const float* __restrict__ feat,
                                              const float* __restrict__ attn_l,
                                              const float* __restrict__ attn_r) {
    __shared__ __nv_bfloat16 sAhi[128 * STR];
    __shared__ __nv_bfloat16 sAlo[128 * STR];
    __shared__ __nv_bfloat16 sBhi[128 * STR];
    __shared__ __nv_bfloat16 sBlo[128 * STR];

    int tid = threadIdx.x;
    int warp = tid >> 5, lane = tid & 31;
    int row0 = blockIdx.x * 128;

    float acc[16][4];
#pragma unroll
    for (int i = 0; i < 16; i++)
#pragma unroll
        for (int j = 0; j < 4; j++) acc[i][j] = 0.f;

    // per-thread load coords: thread t -> row t/2, 16-col half (t&1)
    int lr = tid >> 1;
    int lc = (tid & 1) * 16;
    bool a_valid = (row0 + lr) < Nn;

    uint32_t uAhi = smem_u32(sAhi), uAlo = smem_u32(sAlo);
    uint32_t uBhi = smem_u32(sBhi), uBlo = smem_u32(sBlo);

    // ldmatrix lane addressing: row = base + (lane&15), col = k0 + (lane>>4)*8
    int lm_r = lane & 15;
    int lm_c = (lane >> 4) * 8;

    for (int kk = 0; kk < INF; kk += 32) {
        __syncthreads();
        // ---- load A chunk, split fp32 -> bf16 hi/lo ----
        {
            const float4* src = (const float4*)(feat + (size_t)(row0 + lr) * INF + kk + lc);
            __nv_bfloat162* dh = (__nv_bfloat162*)&sAhi[lr * STR + lc];
            __nv_bfloat162* dl = (__nv_bfloat162*)&sAlo[lr * STR + lc];
#pragma unroll
            for (int i = 0; i < 4; i++) {
                float4 v = a_valid ? src[i] : make_float4(0.f, 0.f, 0.f, 0.f);
                __nv_bfloat16 h0 = __float2bfloat16(v.x), h1 = __float2bfloat16(v.y);
                __nv_bfloat16 h2 = __float2bfloat16(v.z), h3 = __float2bfloat16(v.w);
                dh[i * 2 + 0] = __nv_bfloat162(h0, h1);
                dh[i * 2 + 1] = __nv_bfloat162(h2, h3);
                dl[i * 2 + 0] = __nv_bfloat162(
                    __float2bfloat16(v.x - __bfloat162float(h0)),
                    __float2bfloat16(v.y - __bfloat162float(h1)));
                dl[i * 2 + 1] = __nv_bfloat162(
                    __float2bfloat16(v.z - __bfloat162float(h2)),
                    __float2bfloat16(v.w - __bfloat162float(h3)));
            }
        }
        // ---- load B chunk (already bf16 split, [n][k]) ----
        {
            const uint4* bh = (const uint4*)(g_bhi + (size_t)lr * INF + kk + lc);
            const uint4* bl = (const uint4*)(g_blo + (size_t)lr * INF + kk + lc);
            *(uint4*)&sBhi[lr * STR + lc]     = bh[0];
            *(uint4*)&sBhi[lr * STR + lc + 8] = bh[1];
            *(uint4*)&sBlo[lr * STR + lc]     = bl[0];
            *(uint4*)&sBlo[lr * STR + lc + 8] = bl[1];
        }
        __syncthreads();

        // ---- MMA: 2 k16-steps per chunk ----
#pragma unroll
        for (int ks = 0; ks < 2; ks++) {
            int k0 = ks * 16;
            uint32_t aoff = (uint32_t)(((warp * 16 + lm_r) * STR + k0 + lm_c) * 2);
            uint32_t ah0, ah1, ah2, ah3, al0, al1, al2, al3;
            LDMATRIX_X4(ah0, ah1, ah2, ah3, uAhi + aoff);
            LDMATRIX_X4(al0, al1, al2, al3, uAlo + aoff);
#pragma unroll
            for (int g = 0; g < 8; g++) {
                uint32_t boff = (uint32_t)(((g * 16 + lm_r) * STR + k0 + lm_c) * 2);
                uint32_t q0, q1, q2, q3;
                LDMATRIX_X4(q0, q1, q2, q3, uBhi + boff);
                MMA16816(acc[2 * g],     ah0, ah1, ah2, ah3, q0, q2);
                MMA16816(acc[2 * g + 1], ah0, ah1, ah2, ah3, q1, q3);
                MMA16816(acc[2 * g],     al0, al1, al2, al3, q0, q2);
                MMA16816(acc[2 * g + 1], al0, al1, al2, al3, q1, q3);
                LDMATRIX_X4(q0, q1, q2, q3, uBlo + boff);
                MMA16816(acc[2 * g],     ah0, ah1, ah2, ah3, q0, q2);
                MMA16816(acc[2 * g + 1], ah0, ah1, ah2, ah3, q1, q3);
            }
        }
    }

    // ---- epilogue: store g_ft + fused el/er ----
    int r1 = row0 + warp * 16 + (lane >> 2);
    int r2 = r1 + 8;
    float pl1 = 0.f, pr1 = 0.f, pl2 = 0.f, pr2 = 0.f;
#pragma unroll
    for (int nt = 0; nt < 16; nt++) {
        int c = nt * 8 + (lane & 3) * 2;
        float wl0 = attn_l[c], wl1 = attn_l[c + 1];
        float wr0 = attn_r[c], wr1 = attn_r[c + 1];
        pl1 += acc[nt][0] * wl0 + acc[nt][1] * wl1;
        pr1 += acc[nt][0] * wr0 + acc[nt][1] * wr1;
        pl2 += acc[nt][2] * wl0 + acc[nt][3] * wl1;
        pr2 += acc[nt][2] * wr0 + acc[nt][3] * wr1;
        if (r1 < Nn)
            *(float2*)(g_ft + (size_t)r1 * OUTF + c) = make_float2(acc[nt][0], acc[nt][1]);
        if (r2 < Nn)
            *(float2*)(g_ft + (size_t)r2 * OUTF + c) = make_float2(acc[nt][2], acc[nt][3]);
    }
#pragma unroll
    for (int o = 1; o <= 2; o <<= 1) {
        pl1 += __shfl_xor_sync(0xFFFFFFFFu, pl1, o);
        pr1 += __shfl_xor_sync(0xFFFFFFFFu, pr1, o);
        pl2 += __shfl_xor_sync(0xFFFFFFFFu, pl2, o);
        pr2 += __shfl_xor_sync(0xFFFFFFFFu, pr2, o);
    }
    if ((lane & 3) == 0) {
        if (r1 < Nn) { g_el[r1] = pl1; g_er[r1] = pr1; }
        if (r2 < Nn) { g_el[r2] = pl2; g_er[r2] = pr2; }
    }
}

// ---------------------------------------------------------------------------
// Edge pass: leaky-relu score, exp, segment sums + degree histogram.
// ---------------------------------------------------------------------------
__global__ void k_edge(const float* __restrict__ w,
                       const int* __restrict__ src, const int* __restrict__ dst) {
    int i = blockIdx.x * blockDim.x + threadIdx.x;
    if (i >= Ee) return;
    int s = src[i], d = dst[i];
    float e = g_el[s] + g_er[d];
    e = e > 0.f ? e : NEG_SLOPE * e;
    float z  = expf(e);
    float zw = expf(w[i]);
    g_z[i]  = z;
    g_zw[i] = zw;
    atomicAdd(&g_se[d], z);
    atomicAdd(&g_sw[d], zw);
    atomicAdd(&g_deg[d], 1);
}

// ---------------------------------------------------------------------------
// Three-phase parallel prefix scan of degrees -> CSR offsets + cursors.
// ---------------------------------------------------------------------------
__global__ __launch_bounds__(SCAN_T) void k_scan_a() {
    __shared__ int sh[SCAN_T];
    int t = threadIdx.x;
    int i = blockIdx.x * SCAN_T + t;
    int d = (i < Nn) ? g_deg[i] : 0;
    sh[t] = d;
    __syncthreads();
#pragma unroll
    for (int o = 1; o < SCAN_T; o <<= 1) {
        int v = (t >= o) ? sh[t - o] : 0;
        __syncthreads();
        sh[t] += v;
        __syncthreads();
    }
    if (i < Nn) g_off[i] = sh[t] - d;
    if (t == SCAN_T - 1) g_blk[blockIdx.x] = sh[t];
}

__global__ __launch_bounds__(SCAN_T) void k_scan_b() {
    __shared__ int sh[SCAN_T];
    int t = threadIdx.x;
    int d = (t < SCAN_BLOCKS) ? g_blk[t] : 0;
    sh[t] = d;
    __syncthreads();
#pragma unroll
    for (int o = 1; o < SCAN_T; o <<= 1) {
        int v = (t >= o) ? sh[t - o] : 0;
        __syncthreads();
        sh[t] += v;
        __syncthreads();
    }
    if (t < SCAN_BLOCKS) g_blk[t] = sh[t] - d;
}

__global__ __launch_bounds__(SCAN_T) void k_scan_c() {
    int i = blockIdx.x * SCAN_T + threadIdx.x;
    if (i < Nn) {
        int v = g_off[i] + g_blk[blockIdx.x];
        g_off[i] = v;
        g_cur[i] = v;
    }
    if (i == 0) g_off[Nn] = Ee;
}

// ---------------------------------------------------------------------------
// Scatter: bucket (src, blended-attention) by dst.
// ---------------------------------------------------------------------------
__global__ void k_scatter(const int* __restrict__ src, const int* __restrict__ dst) {
    int i = blockIdx.x * blockDim.x + threadIdx.x;
    if (i >= Ee) return;
    int d = dst[i];
    float a = (1.f - ALPHA) * g_z[i] / g_se[d] + ALPHA * g_zw[i] / g_sw[d];
    int pos = atomicAdd(&g_cur[d], 1);
    g_srcs[pos] = src[i];
    g_as[pos]   = a;
}

// ---------------------------------------------------------------------------
// CSR aggregation: one warp per dst node, accumulate in registers, one store.
// ---------------------------------------------------------------------------
__global__ __launch_bounds__(256) void k_agg_csr(const float* __restrict__ bias,
                                                 float* __restrict__ out) {
    int node = blockIdx.x * 8 + (threadIdx.x >> 5);
    int lane = threadIdx.x & 31;
    if (node >= Nn) return;
    int beg = g_off[node], end = g_off[node + 1];

    float4 acc = *(const float4*)(bias + lane * 4);

    for (int base = beg; base < end; base += 32) {
        int n = min(32, end - base);
        int s = 0;
        float a = 0.f;
        if (lane < n) {
            s = g_srcs[base + lane];
            a = g_as[base + lane];
        }
        for (int j = 0; j < n; j++) {
            int   sj = __shfl_sync(0xFFFFFFFFu, s, j);
            float aj = __shfl_sync(0xFFFFFFFFu, a, j);
            float4 v = *(const float4*)(g_ft + (size_t)sj * OUTF + lane * 4);
            acc.x = fmaf(aj, v.x, acc.x);
            acc.y = fmaf(aj, v.y, acc.y);
            acc.z = fmaf(aj, v.z, acc.z);
            acc.w = fmaf(aj, v.w, acc.w);
        }
    }
    *(float4*)(out + (size_t)node * OUTF + lane * 4) = acc;
}

extern "C" void kernel_launch(void* const* d_in, const int* in_sizes, int n_in,
                              void* d_out, int out_size) {
    const float* feat   = (const float*)d_in[0];
    const float* w      = (const float*)d_in[1];
    const float* fcw    = (const float*)d_in[2];
    const float* attn_l = (const float*)d_in[3];
    const float* attn_r = (const float*)d_in[4];
    const float* bias   = (const float*)d_in[5];
    const int*   src    = (const int*)d_in[6];
    const int*   dst    = (const int*)d_in[7];
    float* out = (float*)d_out;

    k_init_a<<<(Nn + 255) / 256, 256>>>();
    k_init_b<<<(Nn + 255) / 256, 256>>>();
    k_bsplit<<<(INF * OUTF + 255) / 256, 256>>>(fcw);
    k_gemm<<<(Nn + 127) / 128, 256>>>(feat, attn_l, attn_r);   // 4th launch: profiled
    k_edge<<<(Ee + 255) / 256, 256>>>(w, src, dst);
    k_scan_a<<<SCAN_BLOCKS, SCAN_T>>>();
    k_scan_b<<<1, SCAN_T>>>();
    k_scan_c<<<SCAN_BLOCKS, SCAN_T>>>();
    k_scatter<<<(Ee + 255) / 256, 256>>>(src, dst);
    k_agg_csr<<<(Nn + 7) / 8, 256>>>(bias, out);
}

// round 7
// speedup vs baseline: 2.2845x; 1.0624x over previous
#include <cuda_runtime.h>
#include <cuda_bf16.h>
#include <cstdint>

#define Nn 50000
#define Ee 800000
#define INF 256
#define OUTF 128
#define NEG_SLOPE 0.2f
#define ALPHA 0.5f

#define SCAN_T 256
#define SCAN_BLOCKS ((Nn + SCAN_T - 1) / SCAN_T)   // 196

// Scratch (static device globals; no runtime allocation)
__device__ float g_ft[(size_t)Nn * OUTF];   // fc projection [N,128]
__device__ float g_el[Nn];
__device__ float g_er[Nn];
__device__ float g_se[Nn];                  // segment sum exp(e)
__device__ float g_sw[Nn];                  // segment sum exp(w)
__device__ int   g_deg[Nn];                 // in-degree per node
__device__ int   g_off[Nn + 1];             // CSR offsets
__device__ int   g_cur[Nn];                 // scatter cursors
__device__ int   g_blk[SCAN_BLOCKS];        // per-block degree totals
__device__ float g_z[Ee];                   // exp(e)
__device__ float g_zw[Ee];                  // exp(w)
__device__ int2  g_sa[Ee];                  // (src, attention bits) bucketed by dst
// bf16 split of fc_w, transposed to [n][k]
__device__ __nv_bfloat16 g_bhi[OUTF * INF];
__device__ __nv_bfloat16 g_blo[OUTF * INF];

__device__ __forceinline__ uint32_t smem_u32(const void* p) {
    uint32_t a;
    asm("{ .reg .u64 t; cvta.to.shared.u64 t, %1; cvt.u32.u64 %0, t; }"
        : "=r"(a) : "l"(p));
    return a;
}

#define LDMATRIX_X4(q0, q1, q2, q3, addr) \
    asm volatile("ldmatrix.sync.aligned.m8n8.x4.shared.b16 {%0,%1,%2,%3}, [%4];" \
                 : "=r"(q0), "=r"(q1), "=r"(q2), "=r"(q3) : "r"(addr))

#define MMA16816(d, a0, a1, a2, a3, b0, b1) \
    asm volatile("mma.sync.aligned.m16n8k16.row.col.f32.bf16.bf16.f32 " \
                 "{%0,%1,%2,%3}, {%4,%5,%6,%7}, {%8,%9}, {%0,%1,%2,%3};" \
                 : "+f"((d)[0]), "+f"((d)[1]), "+f"((d)[2]), "+f"((d)[3]) \
                 : "r"(a0), "r"(a1), "r"(a2), "r"(a3), "r"(b0), "r"(b1))

__global__ void k_init_a() {
    int i = blockIdx.x * blockDim.x + threadIdx.x;
    if (i < Nn) {
        g_se[i] = 0.f;
        g_sw[i] = 0.f;
    }
}
__global__ void k_init_b() {
    int i = blockIdx.x * blockDim.x + threadIdx.x;
    if (i < Nn) g_deg[i] = 0;
}

// ---------------------------------------------------------------------------
// B split: g_bhi/g_blo[n][k] = bf16 hi/lo of fc_w[k][n]  (transpose, tiny)
// ---------------------------------------------------------------------------
__global__ void k_bsplit(const float* __restrict__ fcw) {
    int idx = blockIdx.x * blockDim.x + threadIdx.x;
    if (idx >= INF * OUTF) return;
    int k = idx >> 7, n = idx & 127;
    float v = fcw[idx];
    __nv_bfloat16 h = __float2bfloat16(v);
    __nv_bfloat16 l = __float2bfloat16(v - __bfloat162float(h));
    g_bhi[n * INF + k] = h;
    g_blo[n * INF + k] = l;
}

// ---------------------------------------------------------------------------
// Tensor-core GEMM (mma.sync bf16, 3-term split): g_ft = feat @ fc_w, fp32 acc.
// Block: 256 threads = 8 warps as 4(M) x 2(N); warp tile m32 x n64.
// Per k16-step/warp: 4 A-LDSM + 8 B-LDSM feed 48 MMAs (LDSM/MMA = 0.25).
// fp32 -> bf16 hi/lo split done in-kernel (feat read once).
// Fused epilogue: g_ft store + el/er dot products.
// ---------------------------------------------------------------------------
#define STR 40   // smem row stride in bf16 (32 data + 8 pad -> conflict-free ldmatrix)

__global__ __launch_bounds__(256) void k_gemm(const float* __restrict__ feat,
                                              const float* __restrict__ attn_l,
                                              const float* __restrict__ attn_r) {
    __shared__ __nv_bfloat16 sAhi[128 * STR];
    __shared__ __nv_bfloat16 sAlo[128 * STR];
    __shared__ __nv_bfloat16 sBhi[128 * STR];
    __shared__ __nv_bfloat16 sBlo[128 * STR];

    int tid = threadIdx.x;
    int warp = tid >> 5, lane = tid & 31;
    int mw = warp & 3;        // M-warp: rows mw*32 .. +32
    int nw = warp >> 2;       // N-warp: cols nw*64 .. +64
    int row0 = blockIdx.x * 128;

    float acc[2][8][4];       // [mtile][n8tile][frag]
#pragma unroll
    for (int i = 0; i < 2; i++)
#pragma unroll
        for (int j = 0; j < 8; j++)
#pragma unroll
            for (int q = 0; q < 4; q++) acc[i][j][q] = 0.f;

    // per-thread load coords: thread t -> row t/2, 16-col half (t&1)
    int lr = tid >> 1;
    int lc = (tid & 1) * 16;
    bool a_valid = (row0 + lr) < Nn;

    uint32_t uAhi = smem_u32(sAhi), uAlo = smem_u32(sAlo);
    uint32_t uBhi = smem_u32(sBhi), uBlo = smem_u32(sBlo);

    // ldmatrix lane addressing: row = base + (lane&15), col = k0 + (lane>>4)*8
    int lm_r = lane & 15;
    int lm_c = (lane >> 4) * 8;

    for (int kk = 0; kk < INF; kk += 32) {
        __syncthreads();
        // ---- load A chunk, split fp32 -> bf16 hi/lo ----
        {
            const float4* src = (const float4*)(feat + (size_t)(row0 + lr) * INF + kk + lc);
            __nv_bfloat162* dh = (__nv_bfloat162*)&sAhi[lr * STR + lc];
            __nv_bfloat162* dl = (__nv_bfloat162*)&sAlo[lr * STR + lc];
#pragma unroll
            for (int i = 0; i < 4; i++) {
                float4 v = a_valid ? src[i] : make_float4(0.f, 0.f, 0.f, 0.f);
                __nv_bfloat16 h0 = __float2bfloat16(v.x), h1 = __float2bfloat16(v.y);
                __nv_bfloat16 h2 = __float2bfloat16(v.z), h3 = __float2bfloat16(v.w);
                dh[i * 2 + 0] = __nv_bfloat162(h0, h1);
                dh[i * 2 + 1] = __nv_bfloat162(h2, h3);
                dl[i * 2 + 0] = __nv_bfloat162(
                    __float2bfloat16(v.x - __bfloat162float(h0)),
                    __float2bfloat16(v.y - __bfloat162float(h1)));
                dl[i * 2 + 1] = __nv_bfloat162(
                    __float2bfloat16(v.z - __bfloat162float(h2)),
                    __float2bfloat16(v.w - __bfloat162float(h3)));
            }
        }
        // ---- load B chunk (already bf16 split, [n][k]) ----
        {
            const uint4* bh = (const uint4*)(g_bhi + (size_t)lr * INF + kk + lc);
            const uint4* bl = (const uint4*)(g_blo + (size_t)lr * INF + kk + lc);
            *(uint4*)&sBhi[lr * STR + lc]     = bh[0];
            *(uint4*)&sBhi[lr * STR + lc + 8] = bh[1];
            *(uint4*)&sBlo[lr * STR + lc]     = bl[0];
            *(uint4*)&sBlo[lr * STR + lc + 8] = bl[1];
        }
        __syncthreads();

        // ---- MMA: 2 k16-steps per chunk ----
#pragma unroll
        for (int ks = 0; ks < 2; ks++) {
            int k0 = ks * 16;
            uint32_t ah[2][4], al[2][4];
#pragma unroll
            for (int mt = 0; mt < 2; mt++) {
                uint32_t aoff = (uint32_t)(((mw * 32 + mt * 16 + lm_r) * STR + k0 + lm_c) * 2);
                LDMATRIX_X4(ah[mt][0], ah[mt][1], ah[mt][2], ah[mt][3], uAhi + aoff);
                LDMATRIX_X4(al[mt][0], al[mt][1], al[mt][2], al[mt][3], uAlo + aoff);
            }
#pragma unroll
            for (int g = 0; g < 4; g++) {       // n16 tiles within warp's n64
                uint32_t boff = (uint32_t)(((nw * 64 + g * 16 + lm_r) * STR + k0 + lm_c) * 2);
                uint32_t q0, q1, q2, q3;
                LDMATRIX_X4(q0, q1, q2, q3, uBhi + boff);
#pragma unroll
                for (int mt = 0; mt < 2; mt++) {
                    MMA16816(acc[mt][2 * g],     ah[mt][0], ah[mt][1], ah[mt][2], ah[mt][3], q0, q2);
                    MMA16816(acc[mt][2 * g + 1], ah[mt][0], ah[mt][1], ah[mt][2], ah[mt][3], q1, q3);
                    MMA16816(acc[mt][2 * g],     al[mt][0], al[mt][1], al[mt][2], al[mt][3], q0, q2);
                    MMA16816(acc[mt][2 * g + 1], al[mt][0], al[mt][1], al[mt][2], al[mt][3], q1, q3);
                }
                LDMATRIX_X4(q0, q1, q2, q3, uBlo + boff);
#pragma unroll
                for (int mt = 0; mt < 2; mt++) {
                    MMA16816(acc[mt][2 * g],     ah[mt][0], ah[mt][1], ah[mt][2], ah[mt][3], q0, q2);
                    MMA16816(acc[mt][2 * g + 1], ah[mt][0], ah[mt][1], ah[mt][2], ah[mt][3], q1, q3);
                }
            }
        }
    }

    // ---- epilogue: store g_ft + fused el/er ----
#pragma unroll
    for (int mt = 0; mt < 2; mt++) {
        int r1 = row0 + mw * 32 + mt * 16 + (lane >> 2);
        int r2 = r1 + 8;
        float pl1 = 0.f, pr1 = 0.f, pl2 = 0.f, pr2 = 0.f;
#pragma unroll
        for (int nt = 0; nt < 8; nt++) {
            int c = nw * 64 + nt * 8 + (lane & 3) * 2;
            float wl0 = attn_l[c], wl1 = attn_l[c + 1];
            float wr0 = attn_r[c], wr1 = attn_r[c + 1];
            pl1 += acc[mt][nt][0] * wl0 + acc[mt][nt][1] * wl1;
            pr1 += acc[mt][nt][0] * wr0 + acc[mt][nt][1] * wr1;
            pl2 += acc[mt][nt][2] * wl0 + acc[mt][nt][3] * wl1;
            pr2 += acc[mt][nt][2] * wr0 + acc[mt][nt][3] * wr1;
            if (r1 < Nn)
                *(float2*)(g_ft + (size_t)r1 * OUTF + c) = make_float2(acc[mt][nt][0], acc[mt][nt][1]);
            if (r2 < Nn)
                *(float2*)(g_ft + (size_t)r2 * OUTF + c) = make_float2(acc[mt][nt][2], acc[mt][nt][3]);
        }
        // reduce over the 4 lanes of the quad (cols), then across the 2 N-warps
        // via atomics-free split: N-warp 0 handles halves; combine through smem.
#pragma unroll
        for (int o = 1; o <= 2; o <<= 1) {
            pl1 += __shfl_xor_sync(0xFFFFFFFFu, pl1, o);
            pr1 += __shfl_xor_sync(0xFFFFFFFFu, pr1, o);
            pl2 += __shfl_xor_sync(0xFFFFFFFFu, pl2, o);
            pr2 += __shfl_xor_sync(0xFFFFFFFFu, pr2, o);
        }
        if ((lane & 3) == 0) {
            // two N-warps each hold a partial over their 64 cols: combine in smem
            // reuse sAhi as scratch (all tiles consumed): layout [mw][mt][row8][2 halves]
            float* scr = (float*)sAhi;
            int ridx = ((mw * 2 + mt) * 8 + (lane >> 2)) * 4;   // 8 rows per mt? lane>>2 in 0..7
            // note: lane>>2 enumerates r1's 8 rows; r2 rows stored at +2 floats
            if (nw == 0) {
                scr[ridx + 0] = pl1; scr[ridx + 1] = pr1;
                scr[ridx + 2] = pl2; scr[ridx + 3] = pr2;
            }
        }
    }
    __syncthreads();
    // N-warp 1 adds its partials and writes final el/er
#pragma unroll
    for (int mt = 0; mt < 2; mt++) {
        int r1 = row0 + mw * 32 + mt * 16 + (lane >> 2);
        int r2 = r1 + 8;
        if (nw == 1 && (lane & 3) == 0) {
            float pl1 = 0.f, pr1 = 0.f, pl2 = 0.f, pr2 = 0.f;
#pragma unroll
            for (int nt = 0; nt < 8; nt++) {
                int c = 64 + nt * 8;   // recompute? partials already reduced above
                (void)c;
            }
            // recompute from acc since shuffle-reduced values were not kept:
            // (cheap: 8 n8 tiles x 2 fma pairs)
#pragma unroll
            for (int nt = 0; nt < 8; nt++) {
                int c = 64 + nt * 8 + 0 * 2;   // lane&3==0 -> col pair base
                float wl0 = attn_l[c], wl1 = attn_l[c + 1];
                float wr0 = attn_r[c], wr1 = attn_r[c + 1];
                pl1 += acc[mt][nt][0] * wl0 + acc[mt][nt][1] * wl1;
                pr1 += acc[mt][nt][0] * wr0 + acc[mt][nt][1] * wr1;
                pl2 += acc[mt][nt][2] * wl0 + acc[mt][nt][3] * wl1;
                pr2 += acc[mt][nt][2] * wr0 + acc[mt][nt][3] * wr1;
            }
            // add the quad-mates' contributions via shuffles (lanes 1..3 inactive
            // here, so instead pull full reduction: redo with all lanes)
            (void)pl1;
        }
    }
    // NOTE: the above nw==1 path is incomplete — use a clean full recompute:
    {
        // Each thread recomputes its quad-partials (kept in regs from epilogue
        // above is gone), so do the reduction properly here for ALL warps:
#pragma unroll
        for (int mt = 0; mt < 2; mt++) {
            float pl1 = 0.f, pr1 = 0.f, pl2 = 0.f, pr2 = 0.f;
#pragma unroll
            for (int nt = 0; nt < 8; nt++) {
                int c = nw * 64 + nt * 8 + (lane & 3) * 2;
                float wl0 = attn_l[c], wl1 = attn_l[c + 1];
                float wr0 = attn_r[c], wr1 = attn_r[c + 1];
                pl1 += acc[mt][nt][0] * wl0 + acc[mt][nt][1] * wl1;
                pr1 += acc[mt][nt][0] * wr0 + acc[mt][nt][1] * wr1;
                pl2 += acc[mt][nt][2] * wl0 + acc[mt][nt][3] * wl1;
                pr2 += acc[mt][nt][2] * wr0 + acc[mt][nt][3] * wr1;
            }
#pragma unroll
            for (int o = 1; o <= 2; o <<= 1) {
                pl1 += __shfl_xor_sync(0xFFFFFFFFu, pl1, o);
                pr1 += __shfl_xor_sync(0xFFFFFFFFu, pr1, o);
                pl2 += __shfl_xor_sync(0xFFFFFFFFu, pl2, o);
                pr2 += __shfl_xor_sync(0xFFFFFFFFu, pr2, o);
            }
            if ((lane & 3) == 0) {
                int r1 = row0 + mw * 32 + mt * 16 + (lane >> 2);
                int r2 = r1 + 8;
                if (nw == 0) {
                    if (r1 < Nn) atomicAdd(&g_el[r1], pl1), atomicAdd(&g_er[r1], pr1);
                    if (r2 < Nn) atomicAdd(&g_el[r2], pl2), atomicAdd(&g_er[r2], pr2);
                } else {
                    if (r1 < Nn) atomicAdd(&g_el[r1], pl1), atomicAdd(&g_er[r1], pr1);
                    if (r2 < Nn) atomicAdd(&g_el[r2], pl2), atomicAdd(&g_er[r2], pr2);
                }
            }
        }
    }
}

// zero el/er before gemm (atomicAdd epilogue needs zeroed targets)
__global__ void k_init_elr() {
    int i = blockIdx.x * blockDim.x + threadIdx.x;
    if (i < Nn) {
        g_el[i] = 0.f;
        g_er[i] = 0.f;
    }
}

// ---------------------------------------------------------------------------
// Edge pass: leaky-relu score, exp, segment sums + degree histogram.
// ---------------------------------------------------------------------------
__global__ void k_edge(const float* __restrict__ w,
                       const int* __restrict__ src, const int* __restrict__ dst) {
    int i = blockIdx.x * blockDim.x + threadIdx.x;
    if (i >= Ee) return;
    int s = src[i], d = dst[i];
    float e = g_el[s] + g_er[d];
    e = e > 0.f ? e : NEG_SLOPE * e;
    float z  = expf(e);
    float zw = expf(w[i]);
    g_z[i]  = z;
    g_zw[i] = zw;
    atomicAdd(&g_se[d], z);
    atomicAdd(&g_sw[d], zw);
    atomicAdd(&g_deg[d], 1);
}

// ---------------------------------------------------------------------------
// Three-phase parallel prefix scan of degrees -> CSR offsets + cursors.
// ---------------------------------------------------------------------------
__global__ __launch_bounds__(SCAN_T) void k_scan_a() {
    __shared__ int sh[SCAN_T];
    int t = threadIdx.x;
    int i = blockIdx.x * SCAN_T + t;
    int d = (i < Nn) ? g_deg[i] : 0;
    sh[t] = d;
    __syncthreads();
#pragma unroll
    for (int o = 1; o < SCAN_T; o <<= 1) {
        int v = (t >= o) ? sh[t - o] : 0;
        __syncthreads();
        sh[t] += v;
        __syncthreads();
    }
    if (i < Nn) g_off[i] = sh[t] - d;
    if (t == SCAN_T - 1) g_blk[blockIdx.x] = sh[t];
}

__global__ __launch_bounds__(SCAN_T) void k_scan_b() {
    __shared__ int sh[SCAN_T];
    int t = threadIdx.x;
    int d = (t < SCAN_BLOCKS) ? g_blk[t] : 0;
    sh[t] = d;
    __syncthreads();
#pragma unroll
    for (int o = 1; o < SCAN_T; o <<= 1) {
        int v = (t >= o) ? sh[t - o] : 0;
        __syncthreads();
        sh[t] += v;
        __syncthreads();
    }
    if (t < SCAN_BLOCKS) g_blk[t] = sh[t] - d;
}

__global__ __launch_bounds__(SCAN_T) void k_scan_c() {
    int i = blockIdx.x * SCAN_T + threadIdx.x;
    if (i < Nn) {
        int v = g_off[i] + g_blk[blockIdx.x];
        g_off[i] = v;
        g_cur[i] = v;
    }
    if (i == 0) g_off[Nn] = Ee;
}

// ---------------------------------------------------------------------------
// Scatter: bucket (src, blended-attention) by dst — single int2 store.
// ---------------------------------------------------------------------------
__global__ void k_scatter(const int* __restrict__ src, const int* __restrict__ dst) {
    int i = blockIdx.x * blockDim.x + threadIdx.x;
    if (i >= Ee) return;
    int d = dst[i];
    float a = (1.f - ALPHA) * g_z[i] / g_se[d] + ALPHA * g_zw[i] / g_sw[d];
    int pos = atomicAdd(&g_cur[d], 1);
    g_sa[pos] = make_int2(src[i], __float_as_int(a));
}

// ---------------------------------------------------------------------------
// CSR aggregation: one warp per dst node, accumulate in registers, one store.
// ---------------------------------------------------------------------------
__global__ __launch_bounds__(256) void k_agg_csr(const float* __restrict__ bias,
                                                 float* __restrict__ out) {
    int node = blockIdx.x * 8 + (threadIdx.x >> 5);
    int lane = threadIdx.x & 31;
    if (node >= Nn) return;
    int beg = g_off[node], end = g_off[node + 1];

    float4 acc = *(const float4*)(bias + lane * 4);

    for (int base = beg; base < end; base += 32) {
        int n = min(32, end - base);
        int s = 0;
        float a = 0.f;
        if (lane < n) {
            int2 sa = g_sa[base + lane];
            s = sa.x;
            a = __int_as_float(sa.y);
        }
        for (int j = 0; j < n; j++) {
            int   sj = __shfl_sync(0xFFFFFFFFu, s, j);
            float aj = __shfl_sync(0xFFFFFFFFu, a, j);
            float4 v = *(const float4*)(g_ft + (size_t)sj * OUTF + lane * 4);
            acc.x = fmaf(aj, v.x, acc.x);
            acc.y = fmaf(aj, v.y, acc.y);
            acc.z = fmaf(aj, v.z, acc.z);
            acc.w = fmaf(aj, v.w, acc.w);
        }
    }
    *(float4*)(out + (size_t)node * OUTF + lane * 4) = acc;
}

extern "C" void kernel_launch(void* const* d_in, const int* in_sizes, int n_in,
                              void* d_out, int out_size) {
    const float* feat   = (const float*)d_in[0];
    const float* w      = (const float*)d_in[1];
    const float* fcw    = (const float*)d_in[2];
    const float* attn_l = (const float*)d_in[3];
    const float* attn_r = (const float*)d_in[4];
    const float* bias   = (const float*)d_in[5];
    const int*   src    = (const int*)d_in[6];
    const int*   dst    = (const int*)d_in[7];
    float* out = (float*)d_out;

    k_init_a<<<(Nn + 255) / 256, 256>>>();
    k_init_b<<<(Nn + 255) / 256, 256>>>();
    k_init_elr<<<(Nn + 255) / 256, 256>>>();
    k_bsplit<<<(INF * OUTF + 255) / 256, 256>>>(fcw);
    k_gemm<<<(Nn + 127) / 128, 256>>>(feat, attn_l, attn_r);
    k_edge<<<(Ee + 255) / 256, 256>>>(w, src, dst);
    k_scan_a<<<SCAN_BLOCKS, SCAN_T>>>();
    k_scan_b<<<1, SCAN_T>>>();
    k_scan_c<<<SCAN_BLOCKS, SCAN_T>>>();
    k_scatter<<<(Ee + 255) / 256, 256>>>(src, dst);
    k_agg_csr<<<(Nn + 7) / 8, 256>>>(bias, out);
}

// round 8
// speedup vs baseline: 2.3625x; 1.0341x over previous
#include <cuda_runtime.h>
#include <cuda_bf16.h>
#include <cstdint>

#define Nn 50000
#define Ee 800000
#define INF 256
#define OUTF 128
#define NEG_SLOPE 0.2f
#define ALPHA 0.5f

#define SCAN_T 256
#define SCAN_BLOCKS ((Nn + SCAN_T - 1) / SCAN_T)   // 196

// Scratch (static device globals; no runtime allocation)
__device__ float g_ft[(size_t)Nn * OUTF];   // fc projection [N,128]
__device__ float g_el[Nn];
__device__ float g_er[Nn];
__device__ float g_se[Nn];                  // segment sum exp(e)
__device__ float g_sw[Nn];                  // segment sum exp(w)
__device__ int   g_deg[Nn];                 // in-degree per node
__device__ int   g_off[Nn + 1];             // CSR offsets
__device__ int   g_cur[Nn];                 // scatter cursors
__device__ int   g_blk[SCAN_BLOCKS];        // per-block degree totals
__device__ float g_z[Ee];                   // exp(e)
__device__ float g_zw[Ee];                  // exp(w)
__device__ int2  g_sa[Ee];                  // (src, attention bits) bucketed by dst
// bf16 split of fc_w, transposed to [n][k]
__device__ __nv_bfloat16 g_bhi[OUTF * INF];
__device__ __nv_bfloat16 g_blo[OUTF * INF];

__device__ __forceinline__ uint32_t smem_u32(const void* p) {
    uint32_t a;
    asm("{ .reg .u64 t; cvta.to.shared.u64 t, %1; cvt.u32.u64 %0, t; }"
        : "=r"(a) : "l"(p));
    return a;
}

#define LDMATRIX_X4(q0, q1, q2, q3, addr) \
    asm volatile("ldmatrix.sync.aligned.m8n8.x4.shared.b16 {%0,%1,%2,%3}, [%4];" \
                 : "=r"(q0), "=r"(q1), "=r"(q2), "=r"(q3) : "r"(addr))

#define MMA16816(d, a0, a1, a2, a3, b0, b1) \
    asm volatile("mma.sync.aligned.m16n8k16.row.col.f32.bf16.bf16.f32 " \
                 "{%0,%1,%2,%3}, {%4,%5,%6,%7}, {%8,%9}, {%0,%1,%2,%3};" \
                 : "+f"((d)[0]), "+f"((d)[1]), "+f"((d)[2]), "+f"((d)[3]) \
                 : "r"(a0), "r"(a1), "r"(a2), "r"(a3), "r"(b0), "r"(b1))

#define CP_ASYNC16(dst, src) \
    asm volatile("cp.async.cg.shared.global [%0], [%1], 16;" :: "r"(dst), "l"(src))
#define CP_ASYNC_WAIT_ALL() asm volatile("cp.async.wait_all;" ::: "memory")

__global__ void k_init_a() {
    int i = blockIdx.x * blockDim.x + threadIdx.x;
    if (i < Nn) {
        g_se[i] = 0.f;
        g_sw[i] = 0.f;
    }
}
__global__ void k_init_b() {
    int i = blockIdx.x * blockDim.x + threadIdx.x;
    if (i < Nn) g_deg[i] = 0;
}

// ---------------------------------------------------------------------------
// B split: g_bhi/g_blo[n][k] = bf16 hi/lo of fc_w[k][n]  (transpose, tiny)
// ---------------------------------------------------------------------------
__global__ void k_bsplit(const float* __restrict__ fcw) {
    int idx = blockIdx.x * blockDim.x + threadIdx.x;
    if (idx >= INF * OUTF) return;
    int k = idx >> 7, n = idx & 127;
    float v = fcw[idx];
    __nv_bfloat16 h = __float2bfloat16(v);
    __nv_bfloat16 l = __float2bfloat16(v - __bfloat162float(h));
    g_bhi[n * INF + k] = h;
    g_blo[n * INF + k] = l;
}

// ---------------------------------------------------------------------------
// Tensor-core GEMM (mma.sync bf16, 3-term split): g_ft = feat @ fc_w, fp32 acc.
// Block: 256 threads = 8 warps as 4(M) x 2(N); warp tile m32 x n64.
// Pipeline: A chunk prefetched to registers across MMA phase; B via cp.async.
// Fused epilogue: g_ft store + el/er dot products (smem-combined, no atomics).
// ---------------------------------------------------------------------------
#define STR 40   // smem row stride in bf16 (32 data + 8 pad -> conflict-free ldmatrix)

__global__ __launch_bounds__(256) void k_gemm(const float* __restrict__ feat,
                                              const float* __restrict__ attn_l,
                                              const float* __restrict__ attn_r) {
    __shared__ __nv_bfloat16 sAhi[128 * STR];
    __shared__ __nv_bfloat16 sAlo[128 * STR];
    __shared__ __nv_bfloat16 sBhi[128 * STR];
    __shared__ __nv_bfloat16 sBlo[128 * STR];

    int tid = threadIdx.x;
    int warp = tid >> 5, lane = tid & 31;
    int mw = warp & 3;        // M-warp: rows mw*32 .. +32
    int nw = warp >> 2;       // N-warp: cols nw*64 .. +64
    int row0 = blockIdx.x * 128;

    float acc[2][8][4];       // [mtile][n8tile][frag]
#pragma unroll
    for (int i = 0; i < 2; i++)
#pragma unroll
        for (int j = 0; j < 8; j++)
#pragma unroll
            for (int q = 0; q < 4; q++) acc[i][j][q] = 0.f;

    // per-thread load coords: thread t -> row t/2, 16-col half (t&1)
    int lr = tid >> 1;
    int lc = (tid & 1) * 16;
    bool a_valid = (row0 + lr) < Nn;
    const float4* a_src = (const float4*)(feat + (size_t)(row0 + lr) * INF + lc);

    uint32_t uAhi = smem_u32(sAhi), uAlo = smem_u32(sAlo);
    uint32_t uBhi = smem_u32(sBhi), uBlo = smem_u32(sBlo);

    // ldmatrix lane addressing: row = base + (lane&15), col = k0 + (lane>>4)*8
    int lm_r = lane & 15;
    int lm_c = (lane >> 4) * 8;

    // prefetch chunk 0 of A into registers
    float4 va[4];
#pragma unroll
    for (int i = 0; i < 4; i++)
        va[i] = a_valid ? a_src[i] : make_float4(0.f, 0.f, 0.f, 0.f);

    for (int kc = 0; kc < 8; kc++) {
        int kk = kc * 32;
        __syncthreads();   // previous chunk's ldsm reads complete

        // ---- B chunk via cp.async (bf16, no conversion) ----
        {
            const char* gh = (const char*)(g_bhi + (size_t)lr * INF + kk + lc);
            const char* gl = (const char*)(g_blo + (size_t)lr * INF + kk + lc);
            uint32_t dh = uBhi + (uint32_t)(lr * STR + lc) * 2;
            uint32_t dl = uBlo + (uint32_t)(lr * STR + lc) * 2;
            CP_ASYNC16(dh, gh);
            CP_ASYNC16(dh + 16, gh + 16);
            CP_ASYNC16(dl, gl);
            CP_ASYNC16(dl + 16, gl + 16);
        }

        // ---- A split from prefetched regs -> smem ----
        {
            __nv_bfloat162* dh = (__nv_bfloat162*)&sAhi[lr * STR + lc];
            __nv_bfloat162* dl = (__nv_bfloat162*)&sAlo[lr * STR + lc];
#pragma unroll
            for (int i = 0; i < 4; i++) {
                float4 v = va[i];
                __nv_bfloat16 h0 = __float2bfloat16(v.x), h1 = __float2bfloat16(v.y);
                __nv_bfloat16 h2 = __float2bfloat16(v.z), h3 = __float2bfloat16(v.w);
                dh[i * 2 + 0] = __nv_bfloat162(h0, h1);
                dh[i * 2 + 1] = __nv_bfloat162(h2, h3);
                dl[i * 2 + 0] = __nv_bfloat162(
                    __float2bfloat16(v.x - __bfloat162float(h0)),
                    __float2bfloat16(v.y - __bfloat162float(h1)));
                dl[i * 2 + 1] = __nv_bfloat162(
                    __float2bfloat16(v.z - __bfloat162float(h2)),
                    __float2bfloat16(v.w - __bfloat162float(h3)));
            }
        }

        // ---- prefetch next A chunk (overlaps with MMAs below) ----
        if (kc < 7) {
            const float4* nxt = a_src + (kk + 32) / 4;
#pragma unroll
            for (int i = 0; i < 4; i++)
                va[i] = a_valid ? nxt[i] : make_float4(0.f, 0.f, 0.f, 0.f);
        }

        CP_ASYNC_WAIT_ALL();
        __syncthreads();

        // ---- MMA: 2 k16-steps per chunk ----
#pragma unroll
        for (int ks = 0; ks < 2; ks++) {
            int k0 = ks * 16;
            uint32_t ah[2][4], al[2][4];
#pragma unroll
            for (int mt = 0; mt < 2; mt++) {
                uint32_t aoff = (uint32_t)(((mw * 32 + mt * 16 + lm_r) * STR + k0 + lm_c) * 2);
                LDMATRIX_X4(ah[mt][0], ah[mt][1], ah[mt][2], ah[mt][3], uAhi + aoff);
                LDMATRIX_X4(al[mt][0], al[mt][1], al[mt][2], al[mt][3], uAlo + aoff);
            }
#pragma unroll
            for (int g = 0; g < 4; g++) {       // n16 tiles within warp's n64
                uint32_t boff = (uint32_t)(((nw * 64 + g * 16 + lm_r) * STR + k0 + lm_c) * 2);
                uint32_t q0, q1, q2, q3;
                LDMATRIX_X4(q0, q1, q2, q3, uBhi + boff);
#pragma unroll
                for (int mt = 0; mt < 2; mt++) {
                    MMA16816(acc[mt][2 * g],     ah[mt][0], ah[mt][1], ah[mt][2], ah[mt][3], q0, q2);
                    MMA16816(acc[mt][2 * g + 1], ah[mt][0], ah[mt][1], ah[mt][2], ah[mt][3], q1, q3);
                    MMA16816(acc[mt][2 * g],     al[mt][0], al[mt][1], al[mt][2], al[mt][3], q0, q2);
                    MMA16816(acc[mt][2 * g + 1], al[mt][0], al[mt][1], al[mt][2], al[mt][3], q1, q3);
                }
                LDMATRIX_X4(q0, q1, q2, q3, uBlo + boff);
#pragma unroll
                for (int mt = 0; mt < 2; mt++) {
                    MMA16816(acc[mt][2 * g],     ah[mt][0], ah[mt][1], ah[mt][2], ah[mt][3], q0, q2);
                    MMA16816(acc[mt][2 * g + 1], ah[mt][0], ah[mt][1], ah[mt][2], ah[mt][3], q1, q3);
                }
            }
        }
    }

    // ---- epilogue: store g_ft + fused el/er (no atomics) ----
    __syncthreads();                    // all MMAs done; smem reusable
    float4* scr = (float4*)sAhi;        // 64 float4 scratch
    float p[2][4];
#pragma unroll
    for (int mt = 0; mt < 2; mt++) {
        int r1 = row0 + mw * 32 + mt * 16 + (lane >> 2);
        int r2 = r1 + 8;
        float pl1 = 0.f, pr1 = 0.f, pl2 = 0.f, pr2 = 0.f;
#pragma unroll
        for (int nt = 0; nt < 8; nt++) {
            int c = nw * 64 + nt * 8 + (lane & 3) * 2;
            float wl0 = attn_l[c], wl1 = attn_l[c + 1];
            float wr0 = attn_r[c], wr1 = attn_r[c + 1];
            pl1 += acc[mt][nt][0] * wl0 + acc[mt][nt][1] * wl1;
            pr1 += acc[mt][nt][0] * wr0 + acc[mt][nt][1] * wr1;
            pl2 += acc[mt][nt][2] * wl0 + acc[mt][nt][3] * wl1;
            pr2 += acc[mt][nt][2] * wr0 + acc[mt][nt][3] * wr1;
            if (r1 < Nn)
                *(float2*)(g_ft + (size_t)r1 * OUTF + c) = make_float2(acc[mt][nt][0], acc[mt][nt][1]);
            if (r2 < Nn)
                *(float2*)(g_ft + (size_t)r2 * OUTF + c) = make_float2(acc[mt][nt][2], acc[mt][nt][3]);
        }
#pragma unroll
        for (int o = 1; o <= 2; o <<= 1) {
            pl1 += __shfl_xor_sync(0xFFFFFFFFu, pl1, o);
            pr1 += __shfl_xor_sync(0xFFFFFFFFu, pr1, o);
            pl2 += __shfl_xor_sync(0xFFFFFFFFu, pl2, o);
            pr2 += __shfl_xor_sync(0xFFFFFFFFu, pr2, o);
        }
        p[mt][0] = pl1; p[mt][1] = pr1; p[mt][2] = pl2; p[mt][3] = pr2;
        if (nw == 0 && (lane & 3) == 0)
            scr[(mw * 2 + mt) * 8 + (lane >> 2)] = make_float4(pl1, pr1, pl2, pr2);
    }
    __syncthreads();
    if (nw == 1 && (lane & 3) == 0) {
#pragma unroll
        for (int mt = 0; mt < 2; mt++) {
            float4 q = scr[(mw * 2 + mt) * 8 + (lane >> 2)];
            int r1 = row0 + mw * 32 + mt * 16 + (lane >> 2);
            int r2 = r1 + 8;
            if (r1 < Nn) { g_el[r1] = q.x + p[mt][0]; g_er[r1] = q.y + p[mt][1]; }
            if (r2 < Nn) { g_el[r2] = q.z + p[mt][2]; g_er[r2] = q.w + p[mt][3]; }
        }
    }
}

// ---------------------------------------------------------------------------
// Edge pass: leaky-relu score, exp, segment sums + degree histogram.
// ---------------------------------------------------------------------------
__global__ void k_edge(const float* __restrict__ w,
                       const int* __restrict__ src, const int* __restrict__ dst) {
    int i = blockIdx.x * blockDim.x + threadIdx.x;
    if (i >= Ee) return;
    int s = src[i], d = dst[i];
    float e = g_el[s] + g_er[d];
    e = e > 0.f ? e : NEG_SLOPE * e;
    float z  = expf(e);
    float zw = expf(w[i]);
    g_z[i]  = z;
    g_zw[i] = zw;
    atomicAdd(&g_se[d], z);
    atomicAdd(&g_sw[d], zw);
    atomicAdd(&g_deg[d], 1);
}

// ---------------------------------------------------------------------------
// Three-phase parallel prefix scan of degrees -> CSR offsets + cursors.
// ---------------------------------------------------------------------------
__global__ __launch_bounds__(SCAN_T) void k_scan_a() {
    __shared__ int sh[SCAN_T];
    int t = threadIdx.x;
    int i = blockIdx.x * SCAN_T + t;
    int d = (i < Nn) ? g_deg[i] : 0;
    sh[t] = d;
    __syncthreads();
#pragma unroll
    for (int o = 1; o < SCAN_T; o <<= 1) {
        int v = (t >= o) ? sh[t - o] : 0;
        __syncthreads();
        sh[t] += v;
        __syncthreads();
    }
    if (i < Nn) g_off[i] = sh[t] - d;
    if (t == SCAN_T - 1) g_blk[blockIdx.x] = sh[t];
}

__global__ __launch_bounds__(SCAN_T) void k_scan_b() {
    __shared__ int sh[SCAN_T];
    int t = threadIdx.x;
    int d = (t < SCAN_BLOCKS) ? g_blk[t] : 0;
    sh[t] = d;
    __syncthreads();
#pragma unroll
    for (int o = 1; o < SCAN_T; o <<= 1) {
        int v = (t >= o) ? sh[t - o] : 0;
        __syncthreads();
        sh[t] += v;
        __syncthreads();
    }
    if (t < SCAN_BLOCKS) g_blk[t] = sh[t] - d;
}

__global__ __launch_bounds__(SCAN_T) void k_scan_c() {
    int i = blockIdx.x * SCAN_T + threadIdx.x;
    if (i < Nn) {
        int v = g_off[i] + g_blk[blockIdx.x];
        g_off[i] = v;
        g_cur[i] = v;
    }
    if (i == 0) g_off[Nn] = Ee;
}

// ---------------------------------------------------------------------------
// Scatter: bucket (src, blended-attention) by dst — single int2 store.
// ---------------------------------------------------------------------------
__global__ void k_scatter(const int* __restrict__ src, const int* __restrict__ dst) {
    int i = blockIdx.x * blockDim.x + threadIdx.x;
    if (i >= Ee) return;
    int d = dst[i];
    float a = (1.f - ALPHA) * g_z[i] / g_se[d] + ALPHA * g_zw[i] / g_sw[d];
    int pos = atomicAdd(&g_cur[d], 1);
    g_sa[pos] = make_int2(src[i], __float_as_int(a));
}

// ---------------------------------------------------------------------------
// CSR aggregation: one warp per dst node, accumulate in registers, one store.
// ---------------------------------------------------------------------------
__global__ __launch_bounds__(256) void k_agg_csr(const float* __restrict__ bias,
                                                 float* __restrict__ out) {
    int node = blockIdx.x * 8 + (threadIdx.x >> 5);
    int lane = threadIdx.x & 31;
    if (node >= Nn) return;
    int beg = g_off[node], end = g_off[node + 1];

    float4 acc = *(const float4*)(bias + lane * 4);

    for (int base = beg; base < end; base += 32) {
        int n = min(32, end - base);
        int s = 0;
        float a = 0.f;
        if (lane < n) {
            int2 sa = g_sa[base + lane];
            s = sa.x;
            a = __int_as_float(sa.y);
        }
        for (int j = 0; j < n; j++) {
            int   sj = __shfl_sync(0xFFFFFFFFu, s, j);
            float aj = __shfl_sync(0xFFFFFFFFu, a, j);
            float4 v = *(const float4*)(g_ft + (size_t)sj * OUTF + lane * 4);
            acc.x = fmaf(aj, v.x, acc.x);
            acc.y = fmaf(aj, v.y, acc.y);
            acc.z = fmaf(aj, v.z, acc.z);
            acc.w = fmaf(aj, v.w, acc.w);
        }
    }
    *(float4*)(out + (size_t)node * OUTF + lane * 4) = acc;
}

extern "C" void kernel_launch(void* const* d_in, const int* in_sizes, int n_in,
                              void* d_out, int out_size) {
    const float* feat   = (const float*)d_in[0];
    const float* w      = (const float*)d_in[1];
    const float* fcw    = (const float*)d_in[2];
    const float* attn_l = (const float*)d_in[3];
    const float* attn_r = (const float*)d_in[4];
    const float* bias   = (const float*)d_in[5];
    const int*   src    = (const int*)d_in[6];
    const int*   dst    = (const int*)d_in[7];
    float* out = (float*)d_out;

    k_init_a<<<(Nn + 255) / 256, 256>>>();
    k_init_b<<<(Nn + 255) / 256, 256>>>();
    k_bsplit<<<(INF * OUTF + 255) / 256, 256>>>(fcw);
    k_gemm<<<(Nn + 127) / 128, 256>>>(feat, attn_l, attn_r);   // 4th launch: profiled
    k_edge<<<(Ee + 255) / 256, 256>>>(w, src, dst);
    k_scan_a<<<SCAN_BLOCKS, SCAN_T>>>();
    k_scan_b<<<1, SCAN_T>>>();
    k_scan_c<<<SCAN_BLOCKS, SCAN_T>>>();
    k_scatter<<<(Ee + 255) / 256, 256>>>(src, dst);
    k_agg_csr<<<(Nn + 7) / 8, 256>>>(bias, out);
}